// round 2
// baseline (speedup 1.0000x reference)
#include <cuda_runtime.h>
#include <math.h>

// ---------------- problem constants ----------------
#define SEQ    2048
#define HIDDEN 2560
#define NH     32
#define NKV    8
#define HD     128
#define GS     128
#define QN     (NH*HD)    // 4096
#define KVN    (NKV*HD)   // 1024
#define REP    (NH/NKV)   // 4

// ---------------- device scratch (no allocations allowed) ----------------
__device__ float g_Wq[HIDDEN*QN];    // 40 MB
__device__ float g_Wk[HIDDEN*KVN];   // 10 MB
__device__ float g_Wv[HIDDEN*KVN];   // 10 MB
__device__ float g_Wo[QN*HIDDEN];    // 40 MB
__device__ float g_q[SEQ*QN];        // 32 MB
__device__ float g_k[SEQ*KVN];       //  8 MB
__device__ float g_v[SEQ*KVN];       //  8 MB
__device__ float g_attn[SEQ*QN];     // 32 MB

__device__ __forceinline__ float* weight_sel(int s) {
    switch (s) {
        case 0: return g_Wq;
        case 1: return g_Wk;
        case 2: return g_Wv;
        default: return g_Wo;
    }
}
__device__ __forceinline__ float* buf_sel(int s) {
    switch (s) {
        case 1: return g_q;
        case 2: return g_k;
        case 3: return g_v;
        default: return g_attn;
    }
}

// ---------------- AWQ int4 dequant ----------------
// qweight: [K/8, N] int32, 8 nibbles along K. w = (nib - zero) * scale.
__global__ void dequant_kernel(const int* __restrict__ qw,
                               const float* __restrict__ sc,
                               const int* __restrict__ qz,
                               int wsel, int K8, int N) {
    int idx = blockIdx.x * blockDim.x + threadIdx.x;
    if (idx >= K8 * N) return;
    float* W = weight_sel(wsel);
    int n  = idx % N;
    int k8 = idx / N;
    int g  = k8 / (GS / 8);            // whole 8-pack lies in one group (GS=128)
    int w  = qw[k8 * N + n];
    float z = (float)qz[g * N + n];
    float s = sc[g * N + n];
#pragma unroll
    for (int j = 0; j < 8; j++) {
        int nib = (w >> (4 * j)) & 15;
        W[(k8 * 8 + j) * N + n] = ((float)nib - z) * s;
    }
}

// ---------------- SGEMM: C[M,N] = A[M,K] * W[K,N] (+bias) ----------------
// BM=BN=128, BK=8, 256 threads, 8x8 register tile per thread.
#define GBM 128
#define GBN 128
#define GBK 8
__global__ __launch_bounds__(256)
void sgemm_kernel(const float* __restrict__ Aext, int asel,
                  int wsel,
                  float* __restrict__ Cext, int csel,
                  const float* __restrict__ bias,
                  int M, int N, int K) {
    __shared__ float As[GBK][GBM];
    __shared__ float Bs[GBK][GBN];

    const float* A = Aext ? Aext : buf_sel(asel);
    const float* B = weight_sel(wsel);
    float*       C = Cext ? Cext : buf_sel(csel);

    int tid = threadIdx.x;
    int tx  = tid % 16;
    int ty  = tid / 16;
    int m0  = blockIdx.y * GBM;
    int n0  = blockIdx.x * GBN;

    int arow  = tid >> 1;            // 0..127
    int acol4 = (tid & 1) * 4;       // 0 or 4
    int brow  = tid >> 5;            // 0..7
    int bcol4 = (tid & 31) * 4;      // 0..124

    float c[8][8];
#pragma unroll
    for (int i = 0; i < 8; i++)
#pragma unroll
        for (int j = 0; j < 8; j++) c[i][j] = 0.f;

    for (int k0 = 0; k0 < K; k0 += GBK) {
        float4 av = *(const float4*)&A[(m0 + arow) * K + k0 + acol4];
        As[acol4 + 0][arow] = av.x;
        As[acol4 + 1][arow] = av.y;
        As[acol4 + 2][arow] = av.z;
        As[acol4 + 3][arow] = av.w;
        *(float4*)&Bs[brow][bcol4] = *(const float4*)&B[(k0 + brow) * N + n0 + bcol4];
        __syncthreads();
#pragma unroll
        for (int kk = 0; kk < GBK; kk++) {
            float4 a0 = *(float4*)&As[kk][ty * 8 + 0];
            float4 a1 = *(float4*)&As[kk][ty * 8 + 4];
            float4 b0 = *(float4*)&Bs[kk][tx * 8 + 0];
            float4 b1 = *(float4*)&Bs[kk][tx * 8 + 4];
            float a[8] = {a0.x, a0.y, a0.z, a0.w, a1.x, a1.y, a1.z, a1.w};
            float b[8] = {b0.x, b0.y, b0.z, b0.w, b1.x, b1.y, b1.z, b1.w};
#pragma unroll
            for (int i = 0; i < 8; i++)
#pragma unroll
                for (int j = 0; j < 8; j++) c[i][j] += a[i] * b[j];
        }
        __syncthreads();
    }

#pragma unroll
    for (int i = 0; i < 8; i++) {
        int row = m0 + ty * 8 + i;
#pragma unroll
        for (int j = 0; j < 8; j += 4) {
            int col = n0 + tx * 8 + j;
            float4 v;
            v.x = c[i][j + 0]; v.y = c[i][j + 1]; v.z = c[i][j + 2]; v.w = c[i][j + 3];
            if (bias) {
                v.x += bias[col + 0]; v.y += bias[col + 1];
                v.z += bias[col + 2]; v.w += bias[col + 3];
            }
            *(float4*)&C[row * N + col] = v;
        }
    }
}

// ---------------- RoPE (in place on g_q / g_k) ----------------
template <int NHEADS>
__global__ void rope_kernel(const float* __restrict__ cosp,
                            const float* __restrict__ sinp) {
    int idx = blockIdx.x * blockDim.x + threadIdx.x;
    if (idx >= SEQ * NHEADS * (HD / 2)) return;
    int half = idx & 63;
    int h    = (idx >> 6) % NHEADS;
    int s    = idx / (64 * NHEADS);
    float* base = (NHEADS == NH ? g_q : g_k) + (s * NHEADS + h) * HD;
    float c  = cosp[s * HD + half];   // cos[d] == cos[d+64]
    float sn = sinp[s * HD + half];
    float x1 = base[half];
    float x2 = base[half + 64];
    base[half]      = x1 * c - x2 * sn;
    base[half + 64] = x2 * c + x1 * sn;
}

// ---------------- flash attention (causal, fp32, GQA) ----------------
// grid: (SEQ/64, NH), 256 threads. BM=BN=64.
#define FBM 64
#define FBN 64
#define KPAD 129
#define PPAD 65
#define FLASH_SMEM_BYTES ((FBM*HD + FBN*KPAD + FBN*HD + FBM*PPAD) * (int)sizeof(float))
__global__ __launch_bounds__(256)
void flash_attn_kernel() {
    extern __shared__ float sm[];
    float* Qs = sm;                       // [64][128]
    float* Ks = Qs + FBM * HD;            // [64][129]
    float* Vs = Ks + FBN * KPAD;          // [64][128]
    float* Ps = Vs + FBN * HD;            // [64][65]

    int tid = threadIdx.x;
    int tx  = tid % 16;
    int ty  = tid / 16;
    int qb  = blockIdx.x;
    int h   = blockIdx.y;
    int kvh = h / REP;
    int r0  = qb * FBM;
    const float scale = 0.0883883476483184f;   // 1/sqrt(128)

    // load Q tile
    for (int l = tid; l < FBM * (HD / 4); l += 256) {
        int r = l >> 5, d4 = (l & 31) * 4;
        *(float4*)&Qs[r * HD + d4] = *(const float4*)&g_q[(r0 + r) * QN + h * HD + d4];
    }

    float m_i[4], l_i[4], acc[4][8];
#pragma unroll
    for (int i = 0; i < 4; i++) {
        m_i[i] = -1e30f; l_i[i] = 0.f;
#pragma unroll
        for (int j = 0; j < 8; j++) acc[i][j] = 0.f;
    }

    int nkb = qb + 1;   // causal: only key blocks <= query block
    for (int kb = 0; kb < nkb; kb++) {
        __syncthreads();
        // load K (padded) and V tiles
        for (int l = tid; l < FBN * (HD / 4); l += 256) {
            int r = l >> 5, d4 = (l & 31) * 4;
            int gofs = (kb * FBN + r) * KVN + kvh * HD + d4;
            float4 kv = *(const float4*)&g_k[gofs];
            Ks[r * KPAD + d4 + 0] = kv.x;
            Ks[r * KPAD + d4 + 1] = kv.y;
            Ks[r * KPAD + d4 + 2] = kv.z;
            Ks[r * KPAD + d4 + 3] = kv.w;
            *(float4*)&Vs[r * HD + d4] = *(const float4*)&g_v[gofs];
        }
        __syncthreads();

        // scores: 4x4 per thread over d=0..127
        float sc4[4][4];
#pragma unroll
        for (int i = 0; i < 4; i++)
#pragma unroll
            for (int j = 0; j < 4; j++) sc4[i][j] = 0.f;
#pragma unroll 4
        for (int d = 0; d < HD; d++) {
            float a[4], b[4];
#pragma unroll
            for (int i = 0; i < 4; i++) a[i] = Qs[(ty * 4 + i) * HD + d];
#pragma unroll
            for (int j = 0; j < 4; j++) b[j] = Ks[(tx * 4 + j) * KPAD + d];
#pragma unroll
            for (int i = 0; i < 4; i++)
#pragma unroll
                for (int j = 0; j < 4; j++) sc4[i][j] += a[i] * b[j];
        }

        bool diag = (kb == qb);
#pragma unroll
        for (int i = 0; i < 4; i++) {
            int row = r0 + ty * 4 + i;
#pragma unroll
            for (int j = 0; j < 4; j++) {
                float v = sc4[i][j] * scale;
                if (diag && (kb * FBN + tx * 4 + j) > row) v = -1e30f;
                sc4[i][j] = v;
            }
        }

        // online softmax per row (reduce across 16 tx threads via shuffle)
#pragma unroll
        for (int i = 0; i < 4; i++) {
            float mx = fmaxf(fmaxf(sc4[i][0], sc4[i][1]), fmaxf(sc4[i][2], sc4[i][3]));
#pragma unroll
            for (int off = 8; off > 0; off >>= 1)
                mx = fmaxf(mx, __shfl_xor_sync(0xffffffffu, mx, off));
            float mnew = fmaxf(m_i[i], mx);
            float psum = 0.f;
#pragma unroll
            for (int j = 0; j < 4; j++) {
                sc4[i][j] = __expf(sc4[i][j] - mnew);
                psum += sc4[i][j];
            }
#pragma unroll
            for (int off = 8; off > 0; off >>= 1)
                psum += __shfl_xor_sync(0xffffffffu, psum, off);
            float alpha = __expf(m_i[i] - mnew);
            l_i[i] = l_i[i] * alpha + psum;
            m_i[i] = mnew;
#pragma unroll
            for (int j = 0; j < 8; j++) acc[i][j] *= alpha;
        }

        // write P to smem
#pragma unroll
        for (int i = 0; i < 4; i++)
#pragma unroll
            for (int j = 0; j < 4; j++)
                Ps[(ty * 4 + i) * PPAD + tx * 4 + j] = sc4[i][j];
        __syncthreads();

        // O += P * V   (4 rows x 8 dims per thread)
#pragma unroll 2
        for (int kk = 0; kk < FBN; kk++) {
            float a[4];
#pragma unroll
            for (int i = 0; i < 4; i++) a[i] = Ps[(ty * 4 + i) * PPAD + kk];
            float4 b0 = *(float4*)&Vs[kk * HD + tx * 8 + 0];
            float4 b1 = *(float4*)&Vs[kk * HD + tx * 8 + 4];
#pragma unroll
            for (int i = 0; i < 4; i++) {
                acc[i][0] += a[i] * b0.x; acc[i][1] += a[i] * b0.y;
                acc[i][2] += a[i] * b0.z; acc[i][3] += a[i] * b0.w;
                acc[i][4] += a[i] * b1.x; acc[i][5] += a[i] * b1.y;
                acc[i][6] += a[i] * b1.z; acc[i][7] += a[i] * b1.w;
            }
        }
    }

    // epilogue
#pragma unroll
    for (int i = 0; i < 4; i++) {
        float inv = 1.0f / l_i[i];
        int row = r0 + ty * 4 + i;
        float4 o0, o1;
        o0.x = acc[i][0] * inv; o0.y = acc[i][1] * inv;
        o0.z = acc[i][2] * inv; o0.w = acc[i][3] * inv;
        o1.x = acc[i][4] * inv; o1.y = acc[i][5] * inv;
        o1.z = acc[i][6] * inv; o1.w = acc[i][7] * inv;
        *(float4*)&g_attn[row * QN + h * HD + tx * 8 + 0] = o0;
        *(float4*)&g_attn[row * QN + h * HD + tx * 8 + 4] = o1;
    }
}

// ---------------- host launch ----------------
extern "C" void kernel_launch(void* const* d_in, const int* in_sizes, int n_in,
                              void* d_out, int out_size) {
    const float* x    = (const float*)d_in[0];
    const float* cosp = (const float*)d_in[1];
    const float* sinp = (const float*)d_in[2];
    const float* q_sc = (const float*)d_in[3];
    const float* q_b  = (const float*)d_in[4];
    const float* k_sc = (const float*)d_in[5];
    const float* k_b  = (const float*)d_in[6];
    const float* v_sc = (const float*)d_in[7];
    const float* v_b  = (const float*)d_in[8];
    const float* o_sc = (const float*)d_in[9];
    const int*   q_qw = (const int*)d_in[10];
    const int*   q_qz = (const int*)d_in[11];
    const int*   k_qw = (const int*)d_in[12];
    const int*   k_qz = (const int*)d_in[13];
    const int*   v_qw = (const int*)d_in[14];
    const int*   v_qz = (const int*)d_in[15];
    const int*   o_qw = (const int*)d_in[16];
    const int*   o_qz = (const int*)d_in[17];
    float* out = (float*)d_out;

    // raise the flash kernel's dynamic-smem cap (eager call, capture-legal,
    // idempotent and deterministic across invocations)
    cudaFuncSetAttribute(flash_attn_kernel,
                         cudaFuncAttributeMaxDynamicSharedMemorySize,
                         FLASH_SMEM_BYTES);

    // dequant all four weights
    {
        int n, thr = 256;
        n = (HIDDEN / 8) * QN;
        dequant_kernel<<<(n + thr - 1) / thr, thr>>>(q_qw, q_sc, q_qz, 0, HIDDEN / 8, QN);
        n = (HIDDEN / 8) * KVN;
        dequant_kernel<<<(n + thr - 1) / thr, thr>>>(k_qw, k_sc, k_qz, 1, HIDDEN / 8, KVN);
        dequant_kernel<<<(n + thr - 1) / thr, thr>>>(v_qw, v_sc, v_qz, 2, HIDDEN / 8, KVN);
        n = (QN / 8) * HIDDEN;
        dequant_kernel<<<(n + thr - 1) / thr, thr>>>(o_qw, o_sc, o_qz, 3, QN / 8, HIDDEN);
    }

    // Q/K/V projections (+bias)
    {
        dim3 b(256);
        dim3 gq(QN / GBN, SEQ / GBM);
        sgemm_kernel<<<gq, b>>>(x, 0, /*W*/0, nullptr, /*C*/1, q_b, SEQ, QN, HIDDEN);
        dim3 gk(KVN / GBN, SEQ / GBM);
        sgemm_kernel<<<gk, b>>>(x, 0, 1, nullptr, 2, k_b, SEQ, KVN, HIDDEN);
        sgemm_kernel<<<gk, b>>>(x, 0, 2, nullptr, 3, v_b, SEQ, KVN, HIDDEN);
    }

    // RoPE
    {
        int nq = SEQ * NH * (HD / 2);
        rope_kernel<NH><<<(nq + 255) / 256, 256>>>(cosp, sinp);
        int nk = SEQ * NKV * (HD / 2);
        rope_kernel<NKV><<<(nk + 255) / 256, 256>>>(cosp, sinp);
    }

    // flash attention
    {
        dim3 grid(SEQ / FBM, NH);
        flash_attn_kernel<<<grid, 256, FLASH_SMEM_BYTES>>>();
    }

    // O projection -> d_out
    {
        dim3 b(256);
        dim3 go(HIDDEN / GBN, SEQ / GBM);
        sgemm_kernel<<<go, b>>>(nullptr, 4, 3, out, 0, nullptr, SEQ, HIDDEN, QN);
    }
}

// round 3
// speedup vs baseline: 1.6424x; 1.6424x over previous
#include <cuda_runtime.h>
#include <cuda_bf16.h>
#include <math.h>
#include <stdint.h>

// ---------------- problem constants ----------------
#define SEQ    2048
#define HIDDEN 2560
#define NH     32
#define NKV    8
#define HD     128
#define GS     128
#define QN     (NH*HD)    // 4096
#define KVN    (NKV*HD)   // 1024
#define REP    (NH/NKV)   // 4

// ---------------- device scratch (no allocations allowed) ----------------
// Weights split hi/lo bf16
__device__ __nv_bfloat16 g_Wq_hi[HIDDEN*QN],  g_Wq_lo[HIDDEN*QN];
__device__ __nv_bfloat16 g_Wk_hi[HIDDEN*KVN], g_Wk_lo[HIDDEN*KVN];
__device__ __nv_bfloat16 g_Wv_hi[HIDDEN*KVN], g_Wv_lo[HIDDEN*KVN];
__device__ __nv_bfloat16 g_Wo_hi[QN*HIDDEN],  g_Wo_lo[QN*HIDDEN];
// Activations split hi/lo bf16
__device__ __nv_bfloat16 g_x_hi[SEQ*HIDDEN], g_x_lo[SEQ*HIDDEN];
__device__ __nv_bfloat16 g_a_hi[SEQ*QN],     g_a_lo[SEQ*QN];
// fp32 intermediates
__device__ float g_q[SEQ*QN];
__device__ float g_k[SEQ*KVN];
__device__ float g_v[SEQ*KVN];

__device__ __forceinline__ void wsel_get(int s, __nv_bfloat16*& hi, __nv_bfloat16*& lo) {
    switch (s) {
        case 0: hi = g_Wq_hi; lo = g_Wq_lo; break;
        case 1: hi = g_Wk_hi; lo = g_Wk_lo; break;
        case 2: hi = g_Wv_hi; lo = g_Wv_lo; break;
        default: hi = g_Wo_hi; lo = g_Wo_lo; break;
    }
}
__device__ __forceinline__ void asel_get(int s, const __nv_bfloat16*& hi, const __nv_bfloat16*& lo) {
    if (s == 0) { hi = g_x_hi; lo = g_x_lo; }
    else        { hi = g_a_hi; lo = g_a_lo; }
}
__device__ __forceinline__ float* csel_get(int s) {
    switch (s) {
        case 1: return g_q;
        case 2: return g_k;
        default: return g_v;
    }
}

__device__ __forceinline__ void split_store(float v, __nv_bfloat16* hi, __nv_bfloat16* lo, size_t idx) {
    __nv_bfloat16 h = __float2bfloat16(v);
    hi[idx] = h;
    lo[idx] = __float2bfloat16(v - __bfloat162float(h));
}

// ---------------- AWQ int4 dequant -> split bf16 ----------------
__global__ void dequant_kernel(const int* __restrict__ qw,
                               const float* __restrict__ sc,
                               const int* __restrict__ qz,
                               int wsel, int K8, int N) {
    int idx = blockIdx.x * blockDim.x + threadIdx.x;
    if (idx >= K8 * N) return;
    __nv_bfloat16 *Whi, *Wlo;
    wsel_get(wsel, Whi, Wlo);
    int n  = idx % N;
    int k8 = idx / N;
    int g  = k8 / (GS / 8);
    int w  = qw[k8 * N + n];
    float z = (float)qz[g * N + n];
    float s = sc[g * N + n];
#pragma unroll
    for (int j = 0; j < 8; j++) {
        int nib = (w >> (4 * j)) & 15;
        float val = ((float)nib - z) * s;
        split_store(val, Whi, Wlo, (size_t)(k8 * 8 + j) * N + n);
    }
}

// ---------------- split x into hi/lo bf16 ----------------
__global__ void splitx_kernel(const float* __restrict__ x) {
    int idx = blockIdx.x * blockDim.x + threadIdx.x;
    if (idx >= SEQ * HIDDEN) return;
    split_store(x[idx], g_x_hi, g_x_lo, idx);
}

// ---------------- mma / ldmatrix helpers ----------------
__device__ __forceinline__ void ldsm_x4(uint32_t (&r)[4], uint32_t addr) {
    asm volatile("ldmatrix.sync.aligned.m8n8.x4.shared.b16 {%0,%1,%2,%3}, [%4];"
                 : "=r"(r[0]), "=r"(r[1]), "=r"(r[2]), "=r"(r[3]) : "r"(addr));
}
__device__ __forceinline__ void ldsm_x4_t(uint32_t (&r)[4], uint32_t addr) {
    asm volatile("ldmatrix.sync.aligned.m8n8.x4.trans.shared.b16 {%0,%1,%2,%3}, [%4];"
                 : "=r"(r[0]), "=r"(r[1]), "=r"(r[2]), "=r"(r[3]) : "r"(addr));
}
__device__ __forceinline__ void mma_bf16(float (&c)[4], const uint32_t (&a)[4],
                                         uint32_t b0, uint32_t b1) {
    asm volatile("mma.sync.aligned.m16n8k16.row.col.f32.bf16.bf16.f32 "
                 "{%0,%1,%2,%3}, {%4,%5,%6,%7}, {%8,%9}, {%0,%1,%2,%3};"
                 : "+f"(c[0]), "+f"(c[1]), "+f"(c[2]), "+f"(c[3])
                 : "r"(a[0]), "r"(a[1]), "r"(a[2]), "r"(a[3]), "r"(b0), "r"(b1));
}

// ---------------- split-bf16 tensor-core GEMM ----------------
// C[M,N] = A[M,K] * W[K,N] (+bias), A/W given as hi/lo bf16 pairs.
// BM=BN=128, BK=32, 256 threads, 8 warps each 32x64.
__global__ __launch_bounds__(256)
void gemm_bf16split_kernel(int asel, int wsel, float* __restrict__ Cext, int csel,
                           const float* __restrict__ bias, int M, int N, int K) {
    __shared__ __nv_bfloat16 sAhi[128 * 32], sAlo[128 * 32];
    __shared__ __nv_bfloat16 sWhi[32 * 128], sWlo[32 * 128];

    const __nv_bfloat16 *Ahi, *Alo;
    asel_get(asel, Ahi, Alo);
    __nv_bfloat16 *Whi_, *Wlo_;
    wsel_get(wsel, Whi_, Wlo_);
    const __nv_bfloat16* Whi = Whi_;
    const __nv_bfloat16* Wlo = Wlo_;
    float* C = Cext ? Cext : csel_get(csel);

    int tid  = threadIdx.x;
    int lane = tid & 31;
    int wid  = tid >> 5;
    int wm   = wid & 3;     // 4 warps along M (32 rows each)
    int wn   = wid >> 2;    // 2 warps along N (64 cols each)
    int m0   = blockIdx.y * 128;
    int n0   = blockIdx.x * 128;

    uint32_t uAhi = (uint32_t)__cvta_generic_to_shared(sAhi);
    uint32_t uAlo = (uint32_t)__cvta_generic_to_shared(sAlo);
    uint32_t uWhi = (uint32_t)__cvta_generic_to_shared(sWhi);
    uint32_t uWlo = (uint32_t)__cvta_generic_to_shared(sWlo);

    float c[2][8][4];
#pragma unroll
    for (int i = 0; i < 2; i++)
#pragma unroll
        for (int j = 0; j < 8; j++)
#pragma unroll
            for (int l = 0; l < 4; l++) c[i][j][l] = 0.f;

    for (int k0 = 0; k0 < K; k0 += 32) {
        // global -> smem (swizzled 16B chunks)
#pragma unroll
        for (int i = 0; i < 2; i++) {
            int idx = tid + i * 256;
            // A tile: 128 rows x 4 chunks (chunk = 8 bf16)
            int arow = idx >> 2, ac = idx & 3;
            int apc  = ac ^ ((arow >> 1) & 3);
            size_t asrc = (size_t)(m0 + arow) * K + k0 + ac * 8;
            *(uint4*)&sAhi[arow * 32 + apc * 8] = *(const uint4*)&Ahi[asrc];
            *(uint4*)&sAlo[arow * 32 + apc * 8] = *(const uint4*)&Alo[asrc];
            // W tile: 32 rows x 16 chunks
            int krow = idx >> 4, wc = idx & 15;
            int wpc  = wc ^ (krow & 7);
            size_t wsrc = (size_t)(k0 + krow) * N + n0 + wc * 8;
            *(uint4*)&sWhi[krow * 128 + wpc * 8] = *(const uint4*)&Whi[wsrc];
            *(uint4*)&sWlo[krow * 128 + wpc * 8] = *(const uint4*)&Wlo[wsrc];
        }
        __syncthreads();

#pragma unroll
        for (int kk = 0; kk < 2; kk++) {   // two k16 halves
            uint32_t ahi[2][4], alo[2][4];
#pragma unroll
            for (int mt = 0; mt < 2; mt++) {
                int row = wm * 32 + mt * 16 + (lane & 15);
                int kc  = kk * 2 + (lane >> 4);
                int pc  = kc ^ ((row >> 1) & 3);
                uint32_t off = (uint32_t)(row * 32 + pc * 8) * 2;
                ldsm_x4(ahi[mt], uAhi + off);
                ldsm_x4(alo[mt], uAlo + off);
            }
#pragma unroll
            for (int np = 0; np < 4; np++) {  // n-pairs of 16 cols
                uint32_t bhi[4], blo[4];
                int krow = kk * 16 + (lane & 15);
                int cc   = wn * 8 + np * 2 + (lane >> 4);
                int pcc  = cc ^ (krow & 7);
                uint32_t off = (uint32_t)(krow * 128 + pcc * 8) * 2;
                ldsm_x4_t(bhi, uWhi + off);
                ldsm_x4_t(blo, uWlo + off);
#pragma unroll
                for (int mt = 0; mt < 2; mt++) {
                    mma_bf16(c[mt][np * 2 + 0], ahi[mt], bhi[0], bhi[1]);
                    mma_bf16(c[mt][np * 2 + 1], ahi[mt], bhi[2], bhi[3]);
                    mma_bf16(c[mt][np * 2 + 0], ahi[mt], blo[0], blo[1]);
                    mma_bf16(c[mt][np * 2 + 1], ahi[mt], blo[2], blo[3]);
                    mma_bf16(c[mt][np * 2 + 0], alo[mt], bhi[0], bhi[1]);
                    mma_bf16(c[mt][np * 2 + 1], alo[mt], bhi[2], bhi[3]);
                }
            }
        }
        __syncthreads();
    }

    // epilogue
#pragma unroll
    for (int mt = 0; mt < 2; mt++) {
        int row = m0 + wm * 32 + mt * 16 + (lane >> 2);
#pragma unroll
        for (int nt = 0; nt < 8; nt++) {
            int col = n0 + wn * 64 + nt * 8 + (lane & 3) * 2;
            float b0 = bias ? bias[col] : 0.f;
            float b1 = bias ? bias[col + 1] : 0.f;
            float2 v0, v1;
            v0.x = c[mt][nt][0] + b0; v0.y = c[mt][nt][1] + b1;
            v1.x = c[mt][nt][2] + b0; v1.y = c[mt][nt][3] + b1;
            *(float2*)&C[(size_t)row * N + col]       = v0;
            *(float2*)&C[(size_t)(row + 8) * N + col] = v1;
        }
    }
}

// ---------------- RoPE (in place on g_q / g_k) ----------------
template <int NHEADS>
__global__ void rope_kernel(const float* __restrict__ cosp,
                            const float* __restrict__ sinp) {
    int idx = blockIdx.x * blockDim.x + threadIdx.x;
    if (idx >= SEQ * NHEADS * (HD / 2)) return;
    int half = idx & 63;
    int h    = (idx >> 6) % NHEADS;
    int s    = idx / (64 * NHEADS);
    float* base = (NHEADS == NH ? g_q : g_k) + (s * NHEADS + h) * HD;
    float c  = cosp[s * HD + half];   // cos[d] == cos[d+64]
    float sn = sinp[s * HD + half];
    float x1 = base[half];
    float x2 = base[half + 64];
    base[half]      = x1 * c - x2 * sn;
    base[half + 64] = x2 * c + x1 * sn;
}

// ---------------- flash attention (causal, fp32, GQA) ----------------
#define FBM 64
#define FBN 64
#define KPAD 129
#define PPAD 65
#define FLASH_SMEM_BYTES ((FBM*HD + FBN*KPAD + FBN*HD + FBM*PPAD) * (int)sizeof(float))
__global__ __launch_bounds__(256)
void flash_attn_kernel() {
    extern __shared__ float sm[];
    float* Qs = sm;                       // [64][128]
    float* Ks = Qs + FBM * HD;            // [64][129]
    float* Vs = Ks + FBN * KPAD;          // [64][128]
    float* Ps = Vs + FBN * HD;            // [64][65]

    int tid = threadIdx.x;
    int tx  = tid % 16;
    int ty  = tid / 16;
    int qb  = blockIdx.x;
    int h   = blockIdx.y;
    int kvh = h / REP;
    int r0  = qb * FBM;
    const float scale = 0.0883883476483184f;   // 1/sqrt(128)

    for (int l = tid; l < FBM * (HD / 4); l += 256) {
        int r = l >> 5, d4 = (l & 31) * 4;
        *(float4*)&Qs[r * HD + d4] = *(const float4*)&g_q[(r0 + r) * QN + h * HD + d4];
    }

    float m_i[4], l_i[4], acc[4][8];
#pragma unroll
    for (int i = 0; i < 4; i++) {
        m_i[i] = -1e30f; l_i[i] = 0.f;
#pragma unroll
        for (int j = 0; j < 8; j++) acc[i][j] = 0.f;
    }

    int nkb = qb + 1;
    for (int kb = 0; kb < nkb; kb++) {
        __syncthreads();
        for (int l = tid; l < FBN * (HD / 4); l += 256) {
            int r = l >> 5, d4 = (l & 31) * 4;
            int gofs = (kb * FBN + r) * KVN + kvh * HD + d4;
            float4 kv = *(const float4*)&g_k[gofs];
            Ks[r * KPAD + d4 + 0] = kv.x;
            Ks[r * KPAD + d4 + 1] = kv.y;
            Ks[r * KPAD + d4 + 2] = kv.z;
            Ks[r * KPAD + d4 + 3] = kv.w;
            *(float4*)&Vs[r * HD + d4] = *(const float4*)&g_v[gofs];
        }
        __syncthreads();

        float sc4[4][4];
#pragma unroll
        for (int i = 0; i < 4; i++)
#pragma unroll
            for (int j = 0; j < 4; j++) sc4[i][j] = 0.f;
#pragma unroll 4
        for (int d = 0; d < HD; d++) {
            float a[4], b[4];
#pragma unroll
            for (int i = 0; i < 4; i++) a[i] = Qs[(ty * 4 + i) * HD + d];
#pragma unroll
            for (int j = 0; j < 4; j++) b[j] = Ks[(tx * 4 + j) * KPAD + d];
#pragma unroll
            for (int i = 0; i < 4; i++)
#pragma unroll
                for (int j = 0; j < 4; j++) sc4[i][j] += a[i] * b[j];
        }

        bool diag = (kb == qb);
#pragma unroll
        for (int i = 0; i < 4; i++) {
            int row = r0 + ty * 4 + i;
#pragma unroll
            for (int j = 0; j < 4; j++) {
                float v = sc4[i][j] * scale;
                if (diag && (kb * FBN + tx * 4 + j) > row) v = -1e30f;
                sc4[i][j] = v;
            }
        }

#pragma unroll
        for (int i = 0; i < 4; i++) {
            float mx = fmaxf(fmaxf(sc4[i][0], sc4[i][1]), fmaxf(sc4[i][2], sc4[i][3]));
#pragma unroll
            for (int off = 8; off > 0; off >>= 1)
                mx = fmaxf(mx, __shfl_xor_sync(0xffffffffu, mx, off));
            float mnew = fmaxf(m_i[i], mx);
            float psum = 0.f;
#pragma unroll
            for (int j = 0; j < 4; j++) {
                sc4[i][j] = __expf(sc4[i][j] - mnew);
                psum += sc4[i][j];
            }
#pragma unroll
            for (int off = 8; off > 0; off >>= 1)
                psum += __shfl_xor_sync(0xffffffffu, psum, off);
            float alpha = __expf(m_i[i] - mnew);
            l_i[i] = l_i[i] * alpha + psum;
            m_i[i] = mnew;
#pragma unroll
            for (int j = 0; j < 8; j++) acc[i][j] *= alpha;
        }

#pragma unroll
        for (int i = 0; i < 4; i++)
#pragma unroll
            for (int j = 0; j < 4; j++)
                Ps[(ty * 4 + i) * PPAD + tx * 4 + j] = sc4[i][j];
        __syncthreads();

#pragma unroll 2
        for (int kk = 0; kk < FBN; kk++) {
            float a[4];
#pragma unroll
            for (int i = 0; i < 4; i++) a[i] = Ps[(ty * 4 + i) * PPAD + kk];
            float4 b0 = *(float4*)&Vs[kk * HD + tx * 8 + 0];
            float4 b1 = *(float4*)&Vs[kk * HD + tx * 8 + 4];
#pragma unroll
            for (int i = 0; i < 4; i++) {
                acc[i][0] += a[i] * b0.x; acc[i][1] += a[i] * b0.y;
                acc[i][2] += a[i] * b0.z; acc[i][3] += a[i] * b0.w;
                acc[i][4] += a[i] * b1.x; acc[i][5] += a[i] * b1.y;
                acc[i][6] += a[i] * b1.z; acc[i][7] += a[i] * b1.w;
            }
        }
    }

    // epilogue: write split bf16 (feeds O-proj tensor-core GEMM directly)
#pragma unroll
    for (int i = 0; i < 4; i++) {
        float inv = 1.0f / l_i[i];
        int row = r0 + ty * 4 + i;
        size_t base = (size_t)row * QN + h * HD + tx * 8;
#pragma unroll
        for (int j = 0; j < 8; j++)
            split_store(acc[i][j] * inv, g_a_hi, g_a_lo, base + j);
    }
}

// ---------------- host launch ----------------
extern "C" void kernel_launch(void* const* d_in, const int* in_sizes, int n_in,
                              void* d_out, int out_size) {
    const float* x    = (const float*)d_in[0];
    const float* cosp = (const float*)d_in[1];
    const float* sinp = (const float*)d_in[2];
    const float* q_sc = (const float*)d_in[3];
    const float* q_b  = (const float*)d_in[4];
    const float* k_sc = (const float*)d_in[5];
    const float* k_b  = (const float*)d_in[6];
    const float* v_sc = (const float*)d_in[7];
    const float* v_b  = (const float*)d_in[8];
    const float* o_sc = (const float*)d_in[9];
    const int*   q_qw = (const int*)d_in[10];
    const int*   q_qz = (const int*)d_in[11];
    const int*   k_qw = (const int*)d_in[12];
    const int*   k_qz = (const int*)d_in[13];
    const int*   v_qw = (const int*)d_in[14];
    const int*   v_qz = (const int*)d_in[15];
    const int*   o_qw = (const int*)d_in[16];
    const int*   o_qz = (const int*)d_in[17];
    float* out = (float*)d_out;

    cudaFuncSetAttribute(flash_attn_kernel,
                         cudaFuncAttributeMaxDynamicSharedMemorySize,
                         FLASH_SMEM_BYTES);

    // dequant weights -> split bf16
    {
        int n, thr = 256;
        n = (HIDDEN / 8) * QN;
        dequant_kernel<<<(n + thr - 1) / thr, thr>>>(q_qw, q_sc, q_qz, 0, HIDDEN / 8, QN);
        n = (HIDDEN / 8) * KVN;
        dequant_kernel<<<(n + thr - 1) / thr, thr>>>(k_qw, k_sc, k_qz, 1, HIDDEN / 8, KVN);
        dequant_kernel<<<(n + thr - 1) / thr, thr>>>(v_qw, v_sc, v_qz, 2, HIDDEN / 8, KVN);
        n = (QN / 8) * HIDDEN;
        dequant_kernel<<<(n + thr - 1) / thr, thr>>>(o_qw, o_sc, o_qz, 3, QN / 8, HIDDEN);
    }

    // split x
    {
        int n = SEQ * HIDDEN;
        splitx_kernel<<<(n + 255) / 256, 256>>>(x);
    }

    // Q/K/V projections (+bias), tensor-core split-bf16
    {
        dim3 b(256);
        gemm_bf16split_kernel<<<dim3(QN / 128, SEQ / 128), b>>>(0, 0, nullptr, 1, q_b, SEQ, QN, HIDDEN);
        gemm_bf16split_kernel<<<dim3(KVN / 128, SEQ / 128), b>>>(0, 1, nullptr, 2, k_b, SEQ, KVN, HIDDEN);
        gemm_bf16split_kernel<<<dim3(KVN / 128, SEQ / 128), b>>>(0, 2, nullptr, 3, v_b, SEQ, KVN, HIDDEN);
    }

    // RoPE
    {
        int nq = SEQ * NH * (HD / 2);
        rope_kernel<NH><<<(nq + 255) / 256, 256>>>(cosp, sinp);
        int nk = SEQ * NKV * (HD / 2);
        rope_kernel<NKV><<<(nk + 255) / 256, 256>>>(cosp, sinp);
    }

    // flash attention (writes split bf16 attn output)
    {
        dim3 grid(SEQ / FBM, NH);
        flash_attn_kernel<<<grid, 256, FLASH_SMEM_BYTES>>>();
    }

    // O projection -> d_out
    {
        gemm_bf16split_kernel<<<dim3(HIDDEN / 128, SEQ / 128), 256>>>(1, 3, out, 0, nullptr, SEQ, HIDDEN, QN);
    }
}

// round 13
// speedup vs baseline: 2.5327x; 1.5421x over previous
#include <cuda_runtime.h>
#include <cuda_bf16.h>
#include <math.h>
#include <stdint.h>

// ---------------- problem constants ----------------
#define SEQ    2048
#define HIDDEN 2560
#define NH     32
#define NKV    8
#define HD     128
#define GS     128
#define QN     (NH*HD)    // 4096
#define KVN    (NKV*HD)   // 1024
#define REP    (NH/NKV)   // 4

// ---------------- device scratch (no allocations allowed) ----------------
__device__ __nv_bfloat16 g_Wq_hi[HIDDEN*QN],  g_Wq_lo[HIDDEN*QN];
__device__ __nv_bfloat16 g_Wk_hi[HIDDEN*KVN], g_Wk_lo[HIDDEN*KVN];
__device__ __nv_bfloat16 g_Wv_hi[HIDDEN*KVN], g_Wv_lo[HIDDEN*KVN];
__device__ __nv_bfloat16 g_Wo_hi[QN*HIDDEN],  g_Wo_lo[QN*HIDDEN];
__device__ __nv_bfloat16 g_x_hi[SEQ*HIDDEN], g_x_lo[SEQ*HIDDEN];
__device__ __nv_bfloat16 g_a_hi[SEQ*QN],     g_a_lo[SEQ*QN];
// fp32 proj outputs (pre-RoPE)
__device__ float g_q[SEQ*QN];
__device__ float g_k[SEQ*KVN];
// split bf16 attention operands
__device__ __nv_bfloat16 g_q_hi[SEQ*QN],  g_q_lo[SEQ*QN];
__device__ __nv_bfloat16 g_k_hi[SEQ*KVN], g_k_lo[SEQ*KVN];
__device__ __nv_bfloat16 g_v_hi[SEQ*KVN], g_v_lo[SEQ*KVN];

__device__ __forceinline__ void wsel_get(int s, __nv_bfloat16*& hi, __nv_bfloat16*& lo) {
    switch (s) {
        case 0: hi = g_Wq_hi; lo = g_Wq_lo; break;
        case 1: hi = g_Wk_hi; lo = g_Wk_lo; break;
        case 2: hi = g_Wv_hi; lo = g_Wv_lo; break;
        default: hi = g_Wo_hi; lo = g_Wo_lo; break;
    }
}
__device__ __forceinline__ void asel_get(int s, const __nv_bfloat16*& hi, const __nv_bfloat16*& lo) {
    if (s == 0) { hi = g_x_hi; lo = g_x_lo; }
    else        { hi = g_a_hi; lo = g_a_lo; }
}
__device__ __forceinline__ float* csel_get(int s) {
    return (s == 1) ? g_q : g_k;
}

__device__ __forceinline__ void split_store(float v, __nv_bfloat16* hi, __nv_bfloat16* lo, size_t idx) {
    __nv_bfloat16 h = __float2bfloat16(v);
    hi[idx] = h;
    lo[idx] = __float2bfloat16(v - __bfloat162float(h));
}

// ---------------- AWQ int4 dequant -> split bf16 ----------------
__global__ void dequant_kernel(const int* __restrict__ qw,
                               const float* __restrict__ sc,
                               const int* __restrict__ qz,
                               int wsel, int K8, int N) {
    int idx = blockIdx.x * blockDim.x + threadIdx.x;
    if (idx >= K8 * N) return;
    __nv_bfloat16 *Whi, *Wlo;
    wsel_get(wsel, Whi, Wlo);
    int n  = idx % N;
    int k8 = idx / N;
    int g  = k8 / (GS / 8);
    int w  = qw[k8 * N + n];
    float z = (float)qz[g * N + n];
    float s = sc[g * N + n];
#pragma unroll
    for (int j = 0; j < 8; j++) {
        int nib = (w >> (4 * j)) & 15;
        float val = ((float)nib - z) * s;
        split_store(val, Whi, Wlo, (size_t)(k8 * 8 + j) * N + n);
    }
}

// ---------------- split x into hi/lo bf16 ----------------
__global__ void splitx_kernel(const float* __restrict__ x) {
    int idx = blockIdx.x * blockDim.x + threadIdx.x;
    if (idx >= SEQ * HIDDEN) return;
    split_store(x[idx], g_x_hi, g_x_lo, idx);
}

// ---------------- mma / ldmatrix helpers ----------------
__device__ __forceinline__ void ldsm_x4(uint32_t (&r)[4], uint32_t addr) {
    asm volatile("ldmatrix.sync.aligned.m8n8.x4.shared.b16 {%0,%1,%2,%3}, [%4];"
                 : "=r"(r[0]), "=r"(r[1]), "=r"(r[2]), "=r"(r[3]) : "r"(addr));
}
__device__ __forceinline__ void ldsm_x4_t(uint32_t (&r)[4], uint32_t addr) {
    asm volatile("ldmatrix.sync.aligned.m8n8.x4.trans.shared.b16 {%0,%1,%2,%3}, [%4];"
                 : "=r"(r[0]), "=r"(r[1]), "=r"(r[2]), "=r"(r[3]) : "r"(addr));
}
__device__ __forceinline__ void mma_bf16(float (&c)[4], const uint32_t (&a)[4],
                                         uint32_t b0, uint32_t b1) {
    asm volatile("mma.sync.aligned.m16n8k16.row.col.f32.bf16.bf16.f32 "
                 "{%0,%1,%2,%3}, {%4,%5,%6,%7}, {%8,%9}, {%0,%1,%2,%3};"
                 : "+f"(c[0]), "+f"(c[1]), "+f"(c[2]), "+f"(c[3])
                 : "r"(a[0]), "r"(a[1]), "r"(a[2]), "r"(a[3]), "r"(b0), "r"(b1));
}
// pack two floats into bf16x2 (a -> lo half, b -> hi half)
__device__ __forceinline__ uint32_t pack2bf(float a, float b) {
    uint32_t r;
    asm("cvt.rn.bf16x2.f32 %0, %1, %2;" : "=r"(r) : "f"(b), "f"(a));
    return r;
}

// ---------------- split-bf16 tensor-core GEMM ----------------
// outmode 0: fp32 -> Cext/csel.  outmode 1: split bf16 -> g_v_hi/g_v_lo.
__global__ __launch_bounds__(256)
void gemm_bf16split_kernel(int asel, int wsel, float* __restrict__ Cext, int csel,
                           const float* __restrict__ bias, int M, int N, int K,
                           int outmode) {
    __shared__ __nv_bfloat16 sAhi[128 * 32], sAlo[128 * 32];
    __shared__ __nv_bfloat16 sWhi[32 * 128], sWlo[32 * 128];

    const __nv_bfloat16 *Ahi, *Alo;
    asel_get(asel, Ahi, Alo);
    __nv_bfloat16 *Whi_, *Wlo_;
    wsel_get(wsel, Whi_, Wlo_);
    const __nv_bfloat16* Whi = Whi_;
    const __nv_bfloat16* Wlo = Wlo_;

    int tid  = threadIdx.x;
    int lane = tid & 31;
    int wid  = tid >> 5;
    int wm   = wid & 3;
    int wn   = wid >> 2;
    int m0   = blockIdx.y * 128;
    int n0   = blockIdx.x * 128;

    uint32_t uAhi = (uint32_t)__cvta_generic_to_shared(sAhi);
    uint32_t uAlo = (uint32_t)__cvta_generic_to_shared(sAlo);
    uint32_t uWhi = (uint32_t)__cvta_generic_to_shared(sWhi);
    uint32_t uWlo = (uint32_t)__cvta_generic_to_shared(sWlo);

    float c[2][8][4];
#pragma unroll
    for (int i = 0; i < 2; i++)
#pragma unroll
        for (int j = 0; j < 8; j++)
#pragma unroll
            for (int l = 0; l < 4; l++) c[i][j][l] = 0.f;

    for (int k0 = 0; k0 < K; k0 += 32) {
#pragma unroll
        for (int i = 0; i < 2; i++) {
            int idx = tid + i * 256;
            int arow = idx >> 2, ac = idx & 3;
            int apc  = ac ^ ((arow >> 1) & 3);
            size_t asrc = (size_t)(m0 + arow) * K + k0 + ac * 8;
            *(uint4*)&sAhi[arow * 32 + apc * 8] = *(const uint4*)&Ahi[asrc];
            *(uint4*)&sAlo[arow * 32 + apc * 8] = *(const uint4*)&Alo[asrc];
            int krow = idx >> 4, wc = idx & 15;
            int wpc  = wc ^ (krow & 7);
            size_t wsrc = (size_t)(k0 + krow) * N + n0 + wc * 8;
            *(uint4*)&sWhi[krow * 128 + wpc * 8] = *(const uint4*)&Whi[wsrc];
            *(uint4*)&sWlo[krow * 128 + wpc * 8] = *(const uint4*)&Wlo[wsrc];
        }
        __syncthreads();

#pragma unroll
        for (int kk = 0; kk < 2; kk++) {
            uint32_t ahi[2][4], alo[2][4];
#pragma unroll
            for (int mt = 0; mt < 2; mt++) {
                int row = wm * 32 + mt * 16 + (lane & 15);
                int kc  = kk * 2 + (lane >> 4);
                int pc  = kc ^ ((row >> 1) & 3);
                uint32_t off = (uint32_t)(row * 32 + pc * 8) * 2;
                ldsm_x4(ahi[mt], uAhi + off);
                ldsm_x4(alo[mt], uAlo + off);
            }
#pragma unroll
            for (int np = 0; np < 4; np++) {
                uint32_t bhi[4], blo[4];
                int krow = kk * 16 + (lane & 15);
                int cc   = wn * 8 + np * 2 + (lane >> 4);
                int pcc  = cc ^ (krow & 7);
                uint32_t off = (uint32_t)(krow * 128 + pcc * 8) * 2;
                ldsm_x4_t(bhi, uWhi + off);
                ldsm_x4_t(blo, uWlo + off);
#pragma unroll
                for (int mt = 0; mt < 2; mt++) {
                    mma_bf16(c[mt][np * 2 + 0], ahi[mt], bhi[0], bhi[1]);
                    mma_bf16(c[mt][np * 2 + 1], ahi[mt], bhi[2], bhi[3]);
                    mma_bf16(c[mt][np * 2 + 0], ahi[mt], blo[0], blo[1]);
                    mma_bf16(c[mt][np * 2 + 1], ahi[mt], blo[2], blo[3]);
                    mma_bf16(c[mt][np * 2 + 0], alo[mt], bhi[0], bhi[1]);
                    mma_bf16(c[mt][np * 2 + 1], alo[mt], bhi[2], bhi[3]);
                }
            }
        }
        __syncthreads();
    }

    float* C = Cext ? Cext : csel_get(csel);
#pragma unroll
    for (int mt = 0; mt < 2; mt++) {
        int row = m0 + wm * 32 + mt * 16 + (lane >> 2);
#pragma unroll
        for (int nt = 0; nt < 8; nt++) {
            int col = n0 + wn * 64 + nt * 8 + (lane & 3) * 2;
            float b0 = bias ? bias[col] : 0.f;
            float b1 = bias ? bias[col + 1] : 0.f;
            float v00 = c[mt][nt][0] + b0, v01 = c[mt][nt][1] + b1;
            float v10 = c[mt][nt][2] + b0, v11 = c[mt][nt][3] + b1;
            if (outmode == 0) {
                float2 p0 = {v00, v01}, p1 = {v10, v11};
                *(float2*)&C[(size_t)row * N + col]       = p0;
                *(float2*)&C[(size_t)(row + 8) * N + col] = p1;
            } else {
                size_t i0 = (size_t)row * N + col;
                size_t i1 = (size_t)(row + 8) * N + col;
                split_store(v00, g_v_hi, g_v_lo, i0);
                split_store(v01, g_v_hi, g_v_lo, i0 + 1);
                split_store(v10, g_v_hi, g_v_lo, i1);
                split_store(v11, g_v_hi, g_v_lo, i1 + 1);
            }
        }
    }
}

// ---------------- RoPE: fp32 in, split bf16 out (Q pre-scaled by 1/sqrt(HD)) ----------------
template <int NHEADS>
__global__ void rope_split_kernel(const float* __restrict__ cosp,
                                  const float* __restrict__ sinp) {
    int idx = blockIdx.x * blockDim.x + threadIdx.x;
    if (idx >= SEQ * NHEADS * (HD / 2)) return;
    int half = idx & 63;
    int h    = (idx >> 6) % NHEADS;
    int s    = idx / (64 * NHEADS);
    const float* base = (NHEADS == NH ? g_q : g_k) + (size_t)(s * NHEADS + h) * HD;
    float c  = cosp[s * HD + half];
    float sn = sinp[s * HD + half];
    float x1 = base[half];
    float x2 = base[half + 64];
    float r1 = x1 * c - x2 * sn;
    float r2 = x2 * c + x1 * sn;
    const float qs = (NHEADS == NH) ? 0.0883883476483184f : 1.0f;  // 1/sqrt(128) folded into Q
    r1 *= qs; r2 *= qs;
    __nv_bfloat16* hi = (NHEADS == NH) ? g_q_hi : g_k_hi;
    __nv_bfloat16* lo = (NHEADS == NH) ? g_q_lo : g_k_lo;
    size_t o = (size_t)(s * NHEADS + h) * HD;
    split_store(r1, hi, lo, o + half);
    split_store(r2, hi, lo, o + half + 64);
}

// ---------------- tensor-core flash attention (causal, split-bf16, GQA) ----------------
// BM=128 (8 warps x 16 rows), BN=64. Q frags in regs; S frags reused as P frags.
#define FLASH_SMEM_BYTES 65536
__global__ __launch_bounds__(256, 1)
void flash_attn_tc_kernel() {
    extern __shared__ __nv_bfloat16 fsm[];
    int tid  = threadIdx.x;
    int lane = tid & 31;
    int wid  = tid >> 5;          // 0..7, 16 rows each
    int qb   = gridDim.x - 1 - blockIdx.x;   // big tiles first
    int h    = blockIdx.y;
    int kvh  = h / REP;
    int r0   = qb * 128;

    // ---- stage Q (hi at fsm[0..16383], lo at fsm[16384..]) ----
    for (int i = tid; i < 128 * 16; i += 256) {
        int row = i >> 4, c = i & 15;
        int pc = c ^ (row & 7);
        size_t src = (size_t)(r0 + row) * QN + h * HD + c * 8;
        *(uint4*)&fsm[row * 128 + pc * 8]         = *(const uint4*)&g_q_hi[src];
        *(uint4*)&fsm[16384 + row * 128 + pc * 8] = *(const uint4*)&g_q_lo[src];
    }
    __syncthreads();

    uint32_t uS = (uint32_t)__cvta_generic_to_shared(fsm);
    uint32_t qhi[8][4], qlo[8][4];
    {
        int mrow = wid * 16 + (lane & 15);
#pragma unroll
        for (int kc = 0; kc < 8; kc++) {
            int ch = kc * 2 + (lane >> 4);
            int pc = ch ^ (mrow & 7);
            uint32_t off = (uint32_t)(mrow * 128 + pc * 8) * 2;
            ldsm_x4(qhi[kc], uS + off);
            ldsm_x4(qlo[kc], uS + 32768 + off);
        }
    }
    __syncthreads();   // Q now in regs; smem free for K/V

    // smem byte offsets: Khi 0, Klo 16384, Vhi 32768, Vlo 49152
    float o_acc[16][4];
#pragma unroll
    for (int i = 0; i < 16; i++)
#pragma unroll
        for (int j = 0; j < 4; j++) o_acc[i][j] = 0.f;
    float m_r[2] = {-1e30f, -1e30f};
    float l_r[2] = {0.f, 0.f};

    // per-lane index pieces
    int krow_base = (lane & 7) + ((lane >> 4) << 3);   // + np*16  (K b-frag row)
    int kch_sel   = (lane >> 3) & 1;                   // + kc*2   (K chunk)
    int vrow_base = (lane & 7) + (((lane >> 3) & 1) << 3);  // + kc*16 (V row)
    int vch_base  = lane >> 4;                              // + np*2  (V chunk)

    int nkb = 2 * qb + 2;
    for (int kb = 0; kb < nkb; kb++) {
        // load K/V hi/lo tiles (64x128 each)
        for (int i = tid; i < 64 * 16; i += 256) {
            int row = i >> 4, c = i & 15;
            int pc = c ^ (row & 7);
            size_t src = (size_t)(kb * 64 + row) * KVN + kvh * HD + c * 8;
            int d = row * 128 + pc * 8;
            *(uint4*)&fsm[d]         = *(const uint4*)&g_k_hi[src];
            *(uint4*)&fsm[8192 + d]  = *(const uint4*)&g_k_lo[src];
            *(uint4*)&fsm[16384 + d] = *(const uint4*)&g_v_hi[src];
            *(uint4*)&fsm[24576 + d] = *(const uint4*)&g_v_lo[src];
        }
        __syncthreads();

        // ---- S = Q K^T (scale pre-folded into Q) ----
        float s[8][4];
#pragma unroll
        for (int i = 0; i < 8; i++)
#pragma unroll
            for (int j = 0; j < 4; j++) s[i][j] = 0.f;

#pragma unroll
        for (int np = 0; np < 4; np++) {
            int nrow = np * 16 + krow_base;
            uint32_t rowoff = (uint32_t)nrow * 256;
            int rx = nrow & 7;
#pragma unroll
            for (int kc = 0; kc < 8; kc++) {
                int pc = (kc * 2 + kch_sel) ^ rx;
                uint32_t off = rowoff + (uint32_t)pc * 16;
                uint32_t bh[4], bl[4];
                ldsm_x4(bh, uS + off);
                ldsm_x4(bl, uS + 16384 + off);
                mma_bf16(s[np * 2 + 0], qhi[kc], bh[0], bh[1]);
                mma_bf16(s[np * 2 + 1], qhi[kc], bh[2], bh[3]);
                mma_bf16(s[np * 2 + 0], qhi[kc], bl[0], bl[1]);
                mma_bf16(s[np * 2 + 1], qhi[kc], bl[2], bl[3]);
                mma_bf16(s[np * 2 + 0], qlo[kc], bh[0], bh[1]);
                mma_bf16(s[np * 2 + 1], qlo[kc], bh[2], bh[3]);
            }
        }

        // ---- causal mask (only last two key blocks need it) ----
        if (kb >= 2 * qb) {
#pragma unroll
            for (int nt = 0; nt < 8; nt++)
#pragma unroll
                for (int e = 0; e < 4; e++) {
                    int col = kb * 64 + nt * 8 + 2 * (lane & 3) + (e & 1);
                    int row = r0 + wid * 16 + (lane >> 2) + (e >> 1) * 8;
                    if (col > row) s[nt][e] = -1e30f;
                }
        }

        // ---- online softmax ----
#pragma unroll
        for (int r = 0; r < 2; r++) {
            float mx = -1e30f;
#pragma unroll
            for (int nt = 0; nt < 8; nt++)
                mx = fmaxf(mx, fmaxf(s[nt][2 * r], s[nt][2 * r + 1]));
            mx = fmaxf(mx, __shfl_xor_sync(0xffffffffu, mx, 1));
            mx = fmaxf(mx, __shfl_xor_sync(0xffffffffu, mx, 2));
            float mnew = fmaxf(m_r[r], mx);
            float alpha = __expf(m_r[r] - mnew);
            m_r[r] = mnew;
            float ps = 0.f;
#pragma unroll
            for (int nt = 0; nt < 8; nt++) {
                s[nt][2 * r]     = __expf(s[nt][2 * r] - mnew);
                s[nt][2 * r + 1] = __expf(s[nt][2 * r + 1] - mnew);
                ps += s[nt][2 * r] + s[nt][2 * r + 1];
            }
            l_r[r] = l_r[r] * alpha + ps;
#pragma unroll
            for (int nt = 0; nt < 16; nt++) {
                o_acc[nt][2 * r]     *= alpha;
                o_acc[nt][2 * r + 1] *= alpha;
            }
        }

        // ---- O += P V  (P = S frags reused; split hi/lo) ----
#pragma unroll
        for (int kc = 0; kc < 4; kc++) {
            float p00 = s[2 * kc][0],     p01 = s[2 * kc][1];
            float p10 = s[2 * kc][2],     p11 = s[2 * kc][3];
            float p20 = s[2 * kc + 1][0], p21 = s[2 * kc + 1][1];
            float p30 = s[2 * kc + 1][2], p31 = s[2 * kc + 1][3];
            uint32_t phi[4], plo[4];
            phi[0] = pack2bf(p00, p01);
            phi[1] = pack2bf(p10, p11);
            phi[2] = pack2bf(p20, p21);
            phi[3] = pack2bf(p30, p31);
            plo[0] = pack2bf(p00 - __bfloat162float(__float2bfloat16(p00)),
                             p01 - __bfloat162float(__float2bfloat16(p01)));
            plo[1] = pack2bf(p10 - __bfloat162float(__float2bfloat16(p10)),
                             p11 - __bfloat162float(__float2bfloat16(p11)));
            plo[2] = pack2bf(p20 - __bfloat162float(__float2bfloat16(p20)),
                             p21 - __bfloat162float(__float2bfloat16(p21)));
            plo[3] = pack2bf(p30 - __bfloat162float(__float2bfloat16(p30)),
                             p31 - __bfloat162float(__float2bfloat16(p31)));

            int krow = kc * 16 + vrow_base;
            uint32_t rowoff = (uint32_t)krow * 256;
            int rx = krow & 7;
#pragma unroll
            for (int np = 0; np < 8; np++) {
                int pc = (np * 2 + vch_base) ^ rx;
                uint32_t off = rowoff + (uint32_t)pc * 16;
                uint32_t vh[4], vl[4];
                ldsm_x4_t(vh, uS + 32768 + off);
                ldsm_x4_t(vl, uS + 49152 + off);
                mma_bf16(o_acc[np * 2 + 0], phi, vh[0], vh[1]);
                mma_bf16(o_acc[np * 2 + 1], phi, vh[2], vh[3]);
                mma_bf16(o_acc[np * 2 + 0], phi, vl[0], vl[1]);
                mma_bf16(o_acc[np * 2 + 1], phi, vl[2], vl[3]);
                mma_bf16(o_acc[np * 2 + 0], plo, vh[0], vh[1]);
                mma_bf16(o_acc[np * 2 + 1], plo, vh[2], vh[3]);
            }
        }
        __syncthreads();   // protect smem before next kb load
    }

    // ---- epilogue: normalize, split-store to g_a ----
    float l0 = l_r[0];
    l0 += __shfl_xor_sync(0xffffffffu, l0, 1);
    l0 += __shfl_xor_sync(0xffffffffu, l0, 2);
    float l1 = l_r[1];
    l1 += __shfl_xor_sync(0xffffffffu, l1, 1);
    l1 += __shfl_xor_sync(0xffffffffu, l1, 2);
    float inv0 = 1.f / l0, inv1 = 1.f / l1;

    int row = r0 + wid * 16 + (lane >> 2);
#pragma unroll
    for (int nt = 0; nt < 16; nt++) {
        int col = h * HD + nt * 8 + 2 * (lane & 3);
        size_t i0 = (size_t)row * QN + col;
        size_t i1 = i0 + (size_t)8 * QN;
        float v0 = o_acc[nt][0] * inv0, v1 = o_acc[nt][1] * inv0;
        float w0 = o_acc[nt][2] * inv1, w1 = o_acc[nt][3] * inv1;
        __nv_bfloat16 h0 = __float2bfloat16(v0), h1 = __float2bfloat16(v1);
        __nv_bfloat16 g0 = __float2bfloat16(w0), g1 = __float2bfloat16(w1);
        __nv_bfloat162 ph; ph.x = h0; ph.y = h1;
        __nv_bfloat162 pg; pg.x = g0; pg.y = g1;
        *(__nv_bfloat162*)&g_a_hi[i0] = ph;
        *(__nv_bfloat162*)&g_a_hi[i1] = pg;
        __nv_bfloat162 pl, pm;
        pl.x = __float2bfloat16(v0 - __bfloat162float(h0));
        pl.y = __float2bfloat16(v1 - __bfloat162float(h1));
        pm.x = __float2bfloat16(w0 - __bfloat162float(g0));
        pm.y = __float2bfloat16(w1 - __bfloat162float(g1));
        *(__nv_bfloat162*)&g_a_lo[i0] = pl;
        *(__nv_bfloat162*)&g_a_lo[i1] = pm;
    }
}

// ---------------- host launch ----------------
extern "C" void kernel_launch(void* const* d_in, const int* in_sizes, int n_in,
                              void* d_out, int out_size) {
    const float* x    = (const float*)d_in[0];
    const float* cosp = (const float*)d_in[1];
    const float* sinp = (const float*)d_in[2];
    const float* q_sc = (const float*)d_in[3];
    const float* q_b  = (const float*)d_in[4];
    const float* k_sc = (const float*)d_in[5];
    const float* k_b  = (const float*)d_in[6];
    const float* v_sc = (const float*)d_in[7];
    const float* v_b  = (const float*)d_in[8];
    const float* o_sc = (const float*)d_in[9];
    const int*   q_qw = (const int*)d_in[10];
    const int*   q_qz = (const int*)d_in[11];
    const int*   k_qw = (const int*)d_in[12];
    const int*   k_qz = (const int*)d_in[13];
    const int*   v_qw = (const int*)d_in[14];
    const int*   v_qz = (const int*)d_in[15];
    const int*   o_qw = (const int*)d_in[16];
    const int*   o_qz = (const int*)d_in[17];
    float* out = (float*)d_out;

    cudaFuncSetAttribute(flash_attn_tc_kernel,
                         cudaFuncAttributeMaxDynamicSharedMemorySize,
                         FLASH_SMEM_BYTES);

    // dequant weights -> split bf16
    {
        int n, thr = 256;
        n = (HIDDEN / 8) * QN;
        dequant_kernel<<<(n + thr - 1) / thr, thr>>>(q_qw, q_sc, q_qz, 0, HIDDEN / 8, QN);
        n = (HIDDEN / 8) * KVN;
        dequant_kernel<<<(n + thr - 1) / thr, thr>>>(k_qw, k_sc, k_qz, 1, HIDDEN / 8, KVN);
        dequant_kernel<<<(n + thr - 1) / thr, thr>>>(v_qw, v_sc, v_qz, 2, HIDDEN / 8, KVN);
        n = (QN / 8) * HIDDEN;
        dequant_kernel<<<(n + thr - 1) / thr, thr>>>(o_qw, o_sc, o_qz, 3, QN / 8, HIDDEN);
    }

    // split x
    splitx_kernel<<<(SEQ * HIDDEN + 255) / 256, 256>>>(x);

    // projections: Q,K -> fp32 (rope follows); V -> split bf16 directly
    {
        dim3 b(256);
        gemm_bf16split_kernel<<<dim3(QN / 128, SEQ / 128), b>>>(0, 0, nullptr, 1, q_b, SEQ, QN, HIDDEN, 0);
        gemm_bf16split_kernel<<<dim3(KVN / 128, SEQ / 128), b>>>(0, 1, nullptr, 2, k_b, SEQ, KVN, HIDDEN, 0);
        gemm_bf16split_kernel<<<dim3(KVN / 128, SEQ / 128), b>>>(0, 2, nullptr, 0, v_b, SEQ, KVN, HIDDEN, 1);
    }

    // RoPE -> split bf16 (Q pre-scaled)
    {
        int nq = SEQ * NH * (HD / 2);
        rope_split_kernel<NH><<<(nq + 255) / 256, 256>>>(cosp, sinp);
        int nk = SEQ * NKV * (HD / 2);
        rope_split_kernel<NKV><<<(nk + 255) / 256, 256>>>(cosp, sinp);
    }

    // tensor-core flash attention
    {
        dim3 grid(SEQ / 128, NH);
        flash_attn_tc_kernel<<<grid, 256, FLASH_SMEM_BYTES>>>();
    }

    // O projection -> d_out
    gemm_bf16split_kernel<<<dim3(HIDDEN / 128, SEQ / 128), 256>>>(1, 3, out, 0, nullptr, SEQ, HIDDEN, QN, 0);
}

// round 14
// speedup vs baseline: 3.4095x; 1.3462x over previous
#include <cuda_runtime.h>
#include <cuda_bf16.h>
#include <math.h>
#include <stdint.h>

// ---------------- problem constants ----------------
#define SEQ    2048
#define HIDDEN 2560
#define NH     32
#define NKV    8
#define HD     128
#define GS     128
#define QN     (NH*HD)    // 4096
#define KVN    (NKV*HD)   // 1024
#define REP    (NH/NKV)   // 4

// ---------------- device scratch (no allocations allowed) ----------------
__device__ __nv_bfloat16 g_Wq_hi[HIDDEN*QN],  g_Wq_lo[HIDDEN*QN];
__device__ __nv_bfloat16 g_Wk_hi[HIDDEN*KVN], g_Wk_lo[HIDDEN*KVN];
__device__ __nv_bfloat16 g_Wv_hi[HIDDEN*KVN], g_Wv_lo[HIDDEN*KVN];
__device__ __nv_bfloat16 g_Wo_hi[QN*HIDDEN],  g_Wo_lo[QN*HIDDEN];
__device__ __nv_bfloat16 g_x_hi[SEQ*HIDDEN], g_x_lo[SEQ*HIDDEN];
__device__ __nv_bfloat16 g_a_hi[SEQ*QN],     g_a_lo[SEQ*QN];
// fp32 proj outputs (pre-RoPE)
__device__ float g_q[SEQ*QN];
__device__ float g_k[SEQ*KVN];
// split bf16 attention operands
__device__ __nv_bfloat16 g_q_hi[SEQ*QN],  g_q_lo[SEQ*QN];
__device__ __nv_bfloat16 g_k_hi[SEQ*KVN], g_k_lo[SEQ*KVN];
__device__ __nv_bfloat16 g_v_hi[SEQ*KVN], g_v_lo[SEQ*KVN];

__device__ __forceinline__ void wsel_get(int s, __nv_bfloat16*& hi, __nv_bfloat16*& lo) {
    switch (s) {
        case 0: hi = g_Wq_hi; lo = g_Wq_lo; break;
        case 1: hi = g_Wk_hi; lo = g_Wk_lo; break;
        case 2: hi = g_Wv_hi; lo = g_Wv_lo; break;
        default: hi = g_Wo_hi; lo = g_Wo_lo; break;
    }
}
__device__ __forceinline__ void asel_get(int s, const __nv_bfloat16*& hi, const __nv_bfloat16*& lo) {
    if (s == 0) { hi = g_x_hi; lo = g_x_lo; }
    else        { hi = g_a_hi; lo = g_a_lo; }
}
__device__ __forceinline__ float* csel_get(int s) {
    return (s == 1) ? g_q : g_k;
}

__device__ __forceinline__ void split_store(float v, __nv_bfloat16* hi, __nv_bfloat16* lo, size_t idx) {
    __nv_bfloat16 h = __float2bfloat16(v);
    hi[idx] = h;
    lo[idx] = __float2bfloat16(v - __bfloat162float(h));
}

// ---------------- AWQ int4 dequant -> split bf16 ----------------
__global__ void dequant_kernel(const int* __restrict__ qw,
                               const float* __restrict__ sc,
                               const int* __restrict__ qz,
                               int wsel, int K8, int N) {
    int idx = blockIdx.x * blockDim.x + threadIdx.x;
    if (idx >= K8 * N) return;
    __nv_bfloat16 *Whi, *Wlo;
    wsel_get(wsel, Whi, Wlo);
    int n  = idx % N;
    int k8 = idx / N;
    int g  = k8 / (GS / 8);
    int w  = qw[k8 * N + n];
    float z = (float)qz[g * N + n];
    float s = sc[g * N + n];
#pragma unroll
    for (int j = 0; j < 8; j++) {
        int nib = (w >> (4 * j)) & 15;
        float val = ((float)nib - z) * s;
        split_store(val, Whi, Wlo, (size_t)(k8 * 8 + j) * N + n);
    }
}

// ---------------- split x into hi/lo bf16 ----------------
__global__ void splitx_kernel(const float* __restrict__ x) {
    int idx = blockIdx.x * blockDim.x + threadIdx.x;
    if (idx >= SEQ * HIDDEN) return;
    split_store(x[idx], g_x_hi, g_x_lo, idx);
}

// ---------------- mma / ldmatrix / cp.async helpers ----------------
__device__ __forceinline__ void ldsm_x4(uint32_t (&r)[4], uint32_t addr) {
    asm volatile("ldmatrix.sync.aligned.m8n8.x4.shared.b16 {%0,%1,%2,%3}, [%4];"
                 : "=r"(r[0]), "=r"(r[1]), "=r"(r[2]), "=r"(r[3]) : "r"(addr));
}
__device__ __forceinline__ void ldsm_x4_t(uint32_t (&r)[4], uint32_t addr) {
    asm volatile("ldmatrix.sync.aligned.m8n8.x4.trans.shared.b16 {%0,%1,%2,%3}, [%4];"
                 : "=r"(r[0]), "=r"(r[1]), "=r"(r[2]), "=r"(r[3]) : "r"(addr));
}
__device__ __forceinline__ void mma_bf16(float (&c)[4], const uint32_t (&a)[4],
                                         uint32_t b0, uint32_t b1) {
    asm volatile("mma.sync.aligned.m16n8k16.row.col.f32.bf16.bf16.f32 "
                 "{%0,%1,%2,%3}, {%4,%5,%6,%7}, {%8,%9}, {%0,%1,%2,%3};"
                 : "+f"(c[0]), "+f"(c[1]), "+f"(c[2]), "+f"(c[3])
                 : "r"(a[0]), "r"(a[1]), "r"(a[2]), "r"(a[3]), "r"(b0), "r"(b1));
}
__device__ __forceinline__ uint32_t pack2bf(float a, float b) {
    uint32_t r;
    asm("cvt.rn.bf16x2.f32 %0, %1, %2;" : "=r"(r) : "f"(b), "f"(a));
    return r;
}
__device__ __forceinline__ void cp_async16(uint32_t saddr, const void* gptr) {
    asm volatile("cp.async.cg.shared.global [%0], [%1], 16;"
                 :: "r"(saddr), "l"(gptr) : "memory");
}
#define CP_COMMIT()  asm volatile("cp.async.commit_group;" ::: "memory")
#define CP_WAIT(n)   asm volatile("cp.async.wait_group %0;" :: "n"(n) : "memory")

// ---------------- split-bf16 tensor-core GEMM, cp.async double-buffered ----------------
// outmode 0: fp32 -> Cext/csel.  outmode 1: split bf16 -> g_v_hi/g_v_lo.
// Stage layout (bytes from stage base): Ahi 0, Alo 8192, Whi 16384, Wlo 24576. Stage stride 32768.
#define GEMM_SMEM_BYTES 65536
__global__ __launch_bounds__(256)
void gemm_bf16split_kernel(int asel, int wsel, float* __restrict__ Cext, int csel,
                           const float* __restrict__ bias, int M, int N, int K,
                           int outmode) {
    extern __shared__ __nv_bfloat16 gsm[];

    const __nv_bfloat16 *Ahi, *Alo;
    asel_get(asel, Ahi, Alo);
    __nv_bfloat16 *Whi_, *Wlo_;
    wsel_get(wsel, Whi_, Wlo_);
    const __nv_bfloat16* Whi = Whi_;
    const __nv_bfloat16* Wlo = Wlo_;

    int tid  = threadIdx.x;
    int lane = tid & 31;
    int wid  = tid >> 5;
    int wm   = wid & 3;
    int wn   = wid >> 2;
    int m0   = blockIdx.y * 128;
    int n0   = blockIdx.x * 128;

    uint32_t uG = (uint32_t)__cvta_generic_to_shared(gsm);

    // per-thread load indices (fixed across tiles)
    int idx0 = tid,      idx1 = tid + 256;
    int arow0 = idx0 >> 2, ac0 = idx0 & 3, apc0 = ac0 ^ ((arow0 >> 1) & 3);
    int arow1 = idx1 >> 2, ac1 = idx1 & 3, apc1 = ac1 ^ ((arow1 >> 1) & 3);
    int krow0 = idx0 >> 4, wc0 = idx0 & 15, wpc0 = wc0 ^ (krow0 & 7);
    int krow1 = idx1 >> 4, wc1 = idx1 & 15, wpc1 = wc1 ^ (krow1 & 7);
    uint32_t ad0 = (uint32_t)(arow0 * 32 + apc0 * 8) * 2;
    uint32_t ad1 = (uint32_t)(arow1 * 32 + apc1 * 8) * 2;
    uint32_t wd0 = (uint32_t)(krow0 * 128 + wpc0 * 8) * 2;
    uint32_t wd1 = (uint32_t)(krow1 * 128 + wpc1 * 8) * 2;

    float c[2][8][4];
#pragma unroll
    for (int i = 0; i < 2; i++)
#pragma unroll
        for (int j = 0; j < 8; j++)
#pragma unroll
            for (int l = 0; l < 4; l++) c[i][j][l] = 0.f;

    int T = K / 32;

    // issue loads for one K-tile into a stage
    auto issue_tile = [&](int kt, int st) {
        int k0 = kt * 32;
        uint32_t sb = uG + (uint32_t)st * 32768u;
        size_t a0 = (size_t)(m0 + arow0) * K + k0 + ac0 * 8;
        size_t a1 = (size_t)(m0 + arow1) * K + k0 + ac1 * 8;
        size_t w0 = (size_t)(k0 + krow0) * N + n0 + wc0 * 8;
        size_t w1 = (size_t)(k0 + krow1) * N + n0 + wc1 * 8;
        cp_async16(sb + ad0,          Ahi + a0);
        cp_async16(sb + ad0 + 8192,   Alo + a0);
        cp_async16(sb + ad1,          Ahi + a1);
        cp_async16(sb + ad1 + 8192,   Alo + a1);
        cp_async16(sb + wd0 + 16384,  Whi + w0);
        cp_async16(sb + wd0 + 24576,  Wlo + w0);
        cp_async16(sb + wd1 + 16384,  Whi + w1);
        cp_async16(sb + wd1 + 24576,  Wlo + w1);
        CP_COMMIT();
    };

    // prologue: tiles 0 and 1
    issue_tile(0, 0);
    issue_tile(1, 1);

    for (int t = 0; t < T; t++) {
        if (t == T - 1) CP_WAIT(0); else CP_WAIT(1);
        __syncthreads();

        uint32_t sb   = uG + (uint32_t)(t & 1) * 32768u;
        uint32_t uA   = sb;
        uint32_t uAlo = sb + 8192;
        uint32_t uW   = sb + 16384;
        uint32_t uWlo = sb + 24576;

#pragma unroll
        for (int kk = 0; kk < 2; kk++) {
            uint32_t ahi[2][4], alo[2][4];
#pragma unroll
            for (int mt = 0; mt < 2; mt++) {
                int row = wm * 32 + mt * 16 + (lane & 15);
                int kc  = kk * 2 + (lane >> 4);
                int pc  = kc ^ ((row >> 1) & 3);
                uint32_t off = (uint32_t)(row * 32 + pc * 8) * 2;
                ldsm_x4(ahi[mt], uA + off);
                ldsm_x4(alo[mt], uAlo + off);
            }
#pragma unroll
            for (int np = 0; np < 4; np++) {
                uint32_t bhi[4], blo[4];
                int krow = kk * 16 + (lane & 15);
                int cc   = wn * 8 + np * 2 + (lane >> 4);
                int pcc  = cc ^ (krow & 7);
                uint32_t off = (uint32_t)(krow * 128 + pcc * 8) * 2;
                ldsm_x4_t(bhi, uW + off);
                ldsm_x4_t(blo, uWlo + off);
#pragma unroll
                for (int mt = 0; mt < 2; mt++) {
                    mma_bf16(c[mt][np * 2 + 0], ahi[mt], bhi[0], bhi[1]);
                    mma_bf16(c[mt][np * 2 + 1], ahi[mt], bhi[2], bhi[3]);
                    mma_bf16(c[mt][np * 2 + 0], ahi[mt], blo[0], blo[1]);
                    mma_bf16(c[mt][np * 2 + 1], ahi[mt], blo[2], blo[3]);
                    mma_bf16(c[mt][np * 2 + 0], alo[mt], bhi[0], bhi[1]);
                    mma_bf16(c[mt][np * 2 + 1], alo[mt], bhi[2], bhi[3]);
                }
            }
        }
        __syncthreads();   // all warps done with stage t&1 before refill
        if (t + 2 < T) issue_tile(t + 2, t & 1);
    }

    float* C = Cext ? Cext : csel_get(csel);
#pragma unroll
    for (int mt = 0; mt < 2; mt++) {
        int row = m0 + wm * 32 + mt * 16 + (lane >> 2);
#pragma unroll
        for (int nt = 0; nt < 8; nt++) {
            int col = n0 + wn * 64 + nt * 8 + (lane & 3) * 2;
            float b0 = bias ? bias[col] : 0.f;
            float b1 = bias ? bias[col + 1] : 0.f;
            float v00 = c[mt][nt][0] + b0, v01 = c[mt][nt][1] + b1;
            float v10 = c[mt][nt][2] + b0, v11 = c[mt][nt][3] + b1;
            if (outmode == 0) {
                float2 p0 = {v00, v01}, p1 = {v10, v11};
                *(float2*)&C[(size_t)row * N + col]       = p0;
                *(float2*)&C[(size_t)(row + 8) * N + col] = p1;
            } else {
                size_t i0 = (size_t)row * N + col;
                size_t i1 = (size_t)(row + 8) * N + col;
                split_store(v00, g_v_hi, g_v_lo, i0);
                split_store(v01, g_v_hi, g_v_lo, i0 + 1);
                split_store(v10, g_v_hi, g_v_lo, i1);
                split_store(v11, g_v_hi, g_v_lo, i1 + 1);
            }
        }
    }
}

// ---------------- RoPE: fp32 in, split bf16 out (Q pre-scaled by 1/sqrt(HD)) ----------------
template <int NHEADS>
__global__ void rope_split_kernel(const float* __restrict__ cosp,
                                  const float* __restrict__ sinp) {
    int idx = blockIdx.x * blockDim.x + threadIdx.x;
    if (idx >= SEQ * NHEADS * (HD / 2)) return;
    int half = idx & 63;
    int h    = (idx >> 6) % NHEADS;
    int s    = idx / (64 * NHEADS);
    const float* base = (NHEADS == NH ? g_q : g_k) + (size_t)(s * NHEADS + h) * HD;
    float c  = cosp[s * HD + half];
    float sn = sinp[s * HD + half];
    float x1 = base[half];
    float x2 = base[half + 64];
    float r1 = x1 * c - x2 * sn;
    float r2 = x2 * c + x1 * sn;
    const float qs = (NHEADS == NH) ? 0.0883883476483184f : 1.0f;  // 1/sqrt(128) folded into Q
    r1 *= qs; r2 *= qs;
    __nv_bfloat16* hi = (NHEADS == NH) ? g_q_hi : g_k_hi;
    __nv_bfloat16* lo = (NHEADS == NH) ? g_q_lo : g_k_lo;
    size_t o = (size_t)(s * NHEADS + h) * HD;
    split_store(r1, hi, lo, o + half);
    split_store(r2, hi, lo, o + half + 64);
}

// ---------------- tensor-core flash attention (causal, split-bf16, GQA) ----------------
// BM=128 (8 warps x 16 rows), BN=64. Q frags in regs; S frags reused as P frags.
#define FLASH_SMEM_BYTES 65536
__global__ __launch_bounds__(256, 1)
void flash_attn_tc_kernel() {
    extern __shared__ __nv_bfloat16 fsm[];
    int tid  = threadIdx.x;
    int lane = tid & 31;
    int wid  = tid >> 5;          // 0..7, 16 rows each
    int qb   = gridDim.x - 1 - blockIdx.x;   // big tiles first
    int h    = blockIdx.y;
    int kvh  = h / REP;
    int r0   = qb * 128;

    // ---- stage Q (hi at fsm[0..16383], lo at fsm[16384..]) ----
    for (int i = tid; i < 128 * 16; i += 256) {
        int row = i >> 4, c = i & 15;
        int pc = c ^ (row & 7);
        size_t src = (size_t)(r0 + row) * QN + h * HD + c * 8;
        *(uint4*)&fsm[row * 128 + pc * 8]         = *(const uint4*)&g_q_hi[src];
        *(uint4*)&fsm[16384 + row * 128 + pc * 8] = *(const uint4*)&g_q_lo[src];
    }
    __syncthreads();

    uint32_t uS = (uint32_t)__cvta_generic_to_shared(fsm);
    uint32_t qhi[8][4], qlo[8][4];
    {
        int mrow = wid * 16 + (lane & 15);
#pragma unroll
        for (int kc = 0; kc < 8; kc++) {
            int ch = kc * 2 + (lane >> 4);
            int pc = ch ^ (mrow & 7);
            uint32_t off = (uint32_t)(mrow * 128 + pc * 8) * 2;
            ldsm_x4(qhi[kc], uS + off);
            ldsm_x4(qlo[kc], uS + 32768 + off);
        }
    }
    __syncthreads();   // Q now in regs; smem free for K/V

    // smem byte offsets: Khi 0, Klo 16384, Vhi 32768, Vlo 49152
    float o_acc[16][4];
#pragma unroll
    for (int i = 0; i < 16; i++)
#pragma unroll
        for (int j = 0; j < 4; j++) o_acc[i][j] = 0.f;
    float m_r[2] = {-1e30f, -1e30f};
    float l_r[2] = {0.f, 0.f};

    // per-lane index pieces
    int krow_base = (lane & 7) + ((lane >> 4) << 3);   // + np*16  (K b-frag row)
    int kch_sel   = (lane >> 3) & 1;                   // + kc*2   (K chunk)
    int vrow_base = (lane & 7) + (((lane >> 3) & 1) << 3);  // + kc*16 (V row)
    int vch_base  = lane >> 4;                              // + np*2  (V chunk)

    int nkb = 2 * qb + 2;
    for (int kb = 0; kb < nkb; kb++) {
        // load K/V hi/lo tiles (64x128 each)
        for (int i = tid; i < 64 * 16; i += 256) {
            int row = i >> 4, c = i & 15;
            int pc = c ^ (row & 7);
            size_t src = (size_t)(kb * 64 + row) * KVN + kvh * HD + c * 8;
            int d = row * 128 + pc * 8;
            *(uint4*)&fsm[d]         = *(const uint4*)&g_k_hi[src];
            *(uint4*)&fsm[8192 + d]  = *(const uint4*)&g_k_lo[src];
            *(uint4*)&fsm[16384 + d] = *(const uint4*)&g_v_hi[src];
            *(uint4*)&fsm[24576 + d] = *(const uint4*)&g_v_lo[src];
        }
        __syncthreads();

        // ---- S = Q K^T (scale pre-folded into Q) ----
        float s[8][4];
#pragma unroll
        for (int i = 0; i < 8; i++)
#pragma unroll
            for (int j = 0; j < 4; j++) s[i][j] = 0.f;

#pragma unroll
        for (int np = 0; np < 4; np++) {
            int nrow = np * 16 + krow_base;
            uint32_t rowoff = (uint32_t)nrow * 256;
            int rx = nrow & 7;
#pragma unroll
            for (int kc = 0; kc < 8; kc++) {
                int pc = (kc * 2 + kch_sel) ^ rx;
                uint32_t off = rowoff + (uint32_t)pc * 16;
                uint32_t bh[4], bl[4];
                ldsm_x4(bh, uS + off);
                ldsm_x4(bl, uS + 16384 + off);
                mma_bf16(s[np * 2 + 0], qhi[kc], bh[0], bh[1]);
                mma_bf16(s[np * 2 + 1], qhi[kc], bh[2], bh[3]);
                mma_bf16(s[np * 2 + 0], qhi[kc], bl[0], bl[1]);
                mma_bf16(s[np * 2 + 1], qhi[kc], bl[2], bl[3]);
                mma_bf16(s[np * 2 + 0], qlo[kc], bh[0], bh[1]);
                mma_bf16(s[np * 2 + 1], qlo[kc], bh[2], bh[3]);
            }
        }

        // ---- causal mask (only last two key blocks need it) ----
        if (kb >= 2 * qb) {
#pragma unroll
            for (int nt = 0; nt < 8; nt++)
#pragma unroll
                for (int e = 0; e < 4; e++) {
                    int col = kb * 64 + nt * 8 + 2 * (lane & 3) + (e & 1);
                    int row = r0 + wid * 16 + (lane >> 2) + (e >> 1) * 8;
                    if (col > row) s[nt][e] = -1e30f;
                }
        }

        // ---- online softmax ----
#pragma unroll
        for (int r = 0; r < 2; r++) {
            float mx = -1e30f;
#pragma unroll
            for (int nt = 0; nt < 8; nt++)
                mx = fmaxf(mx, fmaxf(s[nt][2 * r], s[nt][2 * r + 1]));
            mx = fmaxf(mx, __shfl_xor_sync(0xffffffffu, mx, 1));
            mx = fmaxf(mx, __shfl_xor_sync(0xffffffffu, mx, 2));
            float mnew = fmaxf(m_r[r], mx);
            float alpha = __expf(m_r[r] - mnew);
            m_r[r] = mnew;
            float ps = 0.f;
#pragma unroll
            for (int nt = 0; nt < 8; nt++) {
                s[nt][2 * r]     = __expf(s[nt][2 * r] - mnew);
                s[nt][2 * r + 1] = __expf(s[nt][2 * r + 1] - mnew);
                ps += s[nt][2 * r] + s[nt][2 * r + 1];
            }
            l_r[r] = l_r[r] * alpha + ps;
#pragma unroll
            for (int nt = 0; nt < 16; nt++) {
                o_acc[nt][2 * r]     *= alpha;
                o_acc[nt][2 * r + 1] *= alpha;
            }
        }

        // ---- O += P V  (P = S frags reused; split hi/lo) ----
#pragma unroll
        for (int kc = 0; kc < 4; kc++) {
            float p00 = s[2 * kc][0],     p01 = s[2 * kc][1];
            float p10 = s[2 * kc][2],     p11 = s[2 * kc][3];
            float p20 = s[2 * kc + 1][0], p21 = s[2 * kc + 1][1];
            float p30 = s[2 * kc + 1][2], p31 = s[2 * kc + 1][3];
            uint32_t phi[4], plo[4];
            phi[0] = pack2bf(p00, p01);
            phi[1] = pack2bf(p10, p11);
            phi[2] = pack2bf(p20, p21);
            phi[3] = pack2bf(p30, p31);
            plo[0] = pack2bf(p00 - __bfloat162float(__float2bfloat16(p00)),
                             p01 - __bfloat162float(__float2bfloat16(p01)));
            plo[1] = pack2bf(p10 - __bfloat162float(__float2bfloat16(p10)),
                             p11 - __bfloat162float(__float2bfloat16(p11)));
            plo[2] = pack2bf(p20 - __bfloat162float(__float2bfloat16(p20)),
                             p21 - __bfloat162float(__float2bfloat16(p21)));
            plo[3] = pack2bf(p30 - __bfloat162float(__float2bfloat16(p30)),
                             p31 - __bfloat162float(__float2bfloat16(p31)));

            int krow = kc * 16 + vrow_base;
            uint32_t rowoff = (uint32_t)krow * 256;
            int rx = krow & 7;
#pragma unroll
            for (int np = 0; np < 8; np++) {
                int pc = (np * 2 + vch_base) ^ rx;
                uint32_t off = rowoff + (uint32_t)pc * 16;
                uint32_t vh[4], vl[4];
                ldsm_x4_t(vh, uS + 32768 + off);
                ldsm_x4_t(vl, uS + 49152 + off);
                mma_bf16(o_acc[np * 2 + 0], phi, vh[0], vh[1]);
                mma_bf16(o_acc[np * 2 + 1], phi, vh[2], vh[3]);
                mma_bf16(o_acc[np * 2 + 0], phi, vl[0], vl[1]);
                mma_bf16(o_acc[np * 2 + 1], phi, vl[2], vl[3]);
                mma_bf16(o_acc[np * 2 + 0], plo, vh[0], vh[1]);
                mma_bf16(o_acc[np * 2 + 1], plo, vh[2], vh[3]);
            }
        }
        __syncthreads();   // protect smem before next kb load
    }

    // ---- epilogue: normalize, split-store to g_a ----
    float l0 = l_r[0];
    l0 += __shfl_xor_sync(0xffffffffu, l0, 1);
    l0 += __shfl_xor_sync(0xffffffffu, l0, 2);
    float l1 = l_r[1];
    l1 += __shfl_xor_sync(0xffffffffu, l1, 1);
    l1 += __shfl_xor_sync(0xffffffffu, l1, 2);
    float inv0 = 1.f / l0, inv1 = 1.f / l1;

    int row = r0 + wid * 16 + (lane >> 2);
#pragma unroll
    for (int nt = 0; nt < 16; nt++) {
        int col = h * HD + nt * 8 + 2 * (lane & 3);
        size_t i0 = (size_t)row * QN + col;
        size_t i1 = i0 + (size_t)8 * QN;
        float v0 = o_acc[nt][0] * inv0, v1 = o_acc[nt][1] * inv0;
        float w0 = o_acc[nt][2] * inv1, w1 = o_acc[nt][3] * inv1;
        __nv_bfloat16 h0 = __float2bfloat16(v0), h1 = __float2bfloat16(v1);
        __nv_bfloat16 g0 = __float2bfloat16(w0), g1 = __float2bfloat16(w1);
        __nv_bfloat162 ph; ph.x = h0; ph.y = h1;
        __nv_bfloat162 pg; pg.x = g0; pg.y = g1;
        *(__nv_bfloat162*)&g_a_hi[i0] = ph;
        *(__nv_bfloat162*)&g_a_hi[i1] = pg;
        __nv_bfloat162 pl, pm;
        pl.x = __float2bfloat16(v0 - __bfloat162float(h0));
        pl.y = __float2bfloat16(v1 - __bfloat162float(h1));
        pm.x = __float2bfloat16(w0 - __bfloat162float(g0));
        pm.y = __float2bfloat16(w1 - __bfloat162float(g1));
        *(__nv_bfloat162*)&g_a_lo[i0] = pl;
        *(__nv_bfloat162*)&g_a_lo[i1] = pm;
    }
}

// ---------------- host launch ----------------
extern "C" void kernel_launch(void* const* d_in, const int* in_sizes, int n_in,
                              void* d_out, int out_size) {
    const float* x    = (const float*)d_in[0];
    const float* cosp = (const float*)d_in[1];
    const float* sinp = (const float*)d_in[2];
    const float* q_sc = (const float*)d_in[3];
    const float* q_b  = (const float*)d_in[4];
    const float* k_sc = (const float*)d_in[5];
    const float* k_b  = (const float*)d_in[6];
    const float* v_sc = (const float*)d_in[7];
    const float* v_b  = (const float*)d_in[8];
    const float* o_sc = (const float*)d_in[9];
    const int*   q_qw = (const int*)d_in[10];
    const int*   q_qz = (const int*)d_in[11];
    const int*   k_qw = (const int*)d_in[12];
    const int*   k_qz = (const int*)d_in[13];
    const int*   v_qw = (const int*)d_in[14];
    const int*   v_qz = (const int*)d_in[15];
    const int*   o_qw = (const int*)d_in[16];
    const int*   o_qz = (const int*)d_in[17];
    float* out = (float*)d_out;

    cudaFuncSetAttribute(flash_attn_tc_kernel,
                         cudaFuncAttributeMaxDynamicSharedMemorySize,
                         FLASH_SMEM_BYTES);
    cudaFuncSetAttribute(gemm_bf16split_kernel,
                         cudaFuncAttributeMaxDynamicSharedMemorySize,
                         GEMM_SMEM_BYTES);

    // dequant weights -> split bf16
    {
        int n, thr = 256;
        n = (HIDDEN / 8) * QN;
        dequant_kernel<<<(n + thr - 1) / thr, thr>>>(q_qw, q_sc, q_qz, 0, HIDDEN / 8, QN);
        n = (HIDDEN / 8) * KVN;
        dequant_kernel<<<(n + thr - 1) / thr, thr>>>(k_qw, k_sc, k_qz, 1, HIDDEN / 8, KVN);
        dequant_kernel<<<(n + thr - 1) / thr, thr>>>(v_qw, v_sc, v_qz, 2, HIDDEN / 8, KVN);
        n = (QN / 8) * HIDDEN;
        dequant_kernel<<<(n + thr - 1) / thr, thr>>>(o_qw, o_sc, o_qz, 3, QN / 8, HIDDEN);
    }

    // split x
    splitx_kernel<<<(SEQ * HIDDEN + 255) / 256, 256>>>(x);

    // projections: Q,K -> fp32 (rope follows); V -> split bf16 directly
    {
        dim3 b(256);
        gemm_bf16split_kernel<<<dim3(QN / 128, SEQ / 128), b, GEMM_SMEM_BYTES>>>(0, 0, nullptr, 1, q_b, SEQ, QN, HIDDEN, 0);
        gemm_bf16split_kernel<<<dim3(KVN / 128, SEQ / 128), b, GEMM_SMEM_BYTES>>>(0, 1, nullptr, 2, k_b, SEQ, KVN, HIDDEN, 0);
        gemm_bf16split_kernel<<<dim3(KVN / 128, SEQ / 128), b, GEMM_SMEM_BYTES>>>(0, 2, nullptr, 0, v_b, SEQ, KVN, HIDDEN, 1);
    }

    // RoPE -> split bf16 (Q pre-scaled)
    {
        int nq = SEQ * NH * (HD / 2);
        rope_split_kernel<NH><<<(nq + 255) / 256, 256>>>(cosp, sinp);
        int nk = SEQ * NKV * (HD / 2);
        rope_split_kernel<NKV><<<(nk + 255) / 256, 256>>>(cosp, sinp);
    }

    // tensor-core flash attention
    {
        dim3 grid(SEQ / 128, NH);
        flash_attn_tc_kernel<<<grid, 256, FLASH_SMEM_BYTES>>>();
    }

    // O projection -> d_out
    gemm_bf16split_kernel<<<dim3(HIDDEN / 128, SEQ / 128), 256, GEMM_SMEM_BYTES>>>(1, 3, out, 0, nullptr, SEQ, HIDDEN, QN, 0);
}

// round 15
// speedup vs baseline: 3.6618x; 1.0740x over previous
#include <cuda_runtime.h>
#include <cuda_bf16.h>
#include <math.h>
#include <stdint.h>

// ---------------- problem constants ----------------
#define SEQ    2048
#define HIDDEN 2560
#define NH     32
#define NKV    8
#define HD     128
#define GS     128
#define QN     (NH*HD)    // 4096
#define KVN    (NKV*HD)   // 1024
#define REP    (NH/NKV)   // 4

// ---------------- device scratch (no allocations allowed) ----------------
__device__ __nv_bfloat16 g_Wq_hi[HIDDEN*QN],  g_Wq_lo[HIDDEN*QN];
__device__ __nv_bfloat16 g_Wk_hi[HIDDEN*KVN], g_Wk_lo[HIDDEN*KVN];
__device__ __nv_bfloat16 g_Wv_hi[HIDDEN*KVN], g_Wv_lo[HIDDEN*KVN];
__device__ __nv_bfloat16 g_Wo_hi[QN*HIDDEN],  g_Wo_lo[QN*HIDDEN];
__device__ __nv_bfloat16 g_x_hi[SEQ*HIDDEN], g_x_lo[SEQ*HIDDEN];
__device__ __nv_bfloat16 g_a_hi[SEQ*QN],     g_a_lo[SEQ*QN];
// fp32 proj outputs (pre-RoPE)
__device__ float g_q[SEQ*QN];
__device__ float g_k[SEQ*KVN];
// split bf16 attention operands
__device__ __nv_bfloat16 g_q_hi[SEQ*QN],  g_q_lo[SEQ*QN];
__device__ __nv_bfloat16 g_k_hi[SEQ*KVN], g_k_lo[SEQ*KVN];
__device__ __nv_bfloat16 g_v_hi[SEQ*KVN], g_v_lo[SEQ*KVN];

__device__ __forceinline__ void wsel_get(int s, __nv_bfloat16*& hi, __nv_bfloat16*& lo) {
    switch (s) {
        case 0: hi = g_Wq_hi; lo = g_Wq_lo; break;
        case 1: hi = g_Wk_hi; lo = g_Wk_lo; break;
        case 2: hi = g_Wv_hi; lo = g_Wv_lo; break;
        default: hi = g_Wo_hi; lo = g_Wo_lo; break;
    }
}
__device__ __forceinline__ void asel_get(int s, const __nv_bfloat16*& hi, const __nv_bfloat16*& lo) {
    if (s == 0) { hi = g_x_hi; lo = g_x_lo; }
    else        { hi = g_a_hi; lo = g_a_lo; }
}
__device__ __forceinline__ float* csel_get(int s) {
    return (s == 1) ? g_q : g_k;
}

__device__ __forceinline__ void split_store(float v, __nv_bfloat16* hi, __nv_bfloat16* lo, size_t idx) {
    __nv_bfloat16 h = __float2bfloat16(v);
    hi[idx] = h;
    lo[idx] = __float2bfloat16(v - __bfloat162float(h));
}

// ---------------- AWQ int4 dequant -> split bf16 ----------------
__global__ void dequant_kernel(const int* __restrict__ qw,
                               const float* __restrict__ sc,
                               const int* __restrict__ qz,
                               int wsel, int K8, int N) {
    int idx = blockIdx.x * blockDim.x + threadIdx.x;
    if (idx >= K8 * N) return;
    __nv_bfloat16 *Whi, *Wlo;
    wsel_get(wsel, Whi, Wlo);
    int n  = idx % N;
    int k8 = idx / N;
    int g  = k8 / (GS / 8);
    int w  = qw[k8 * N + n];
    float z = (float)qz[g * N + n];
    float s = sc[g * N + n];
#pragma unroll
    for (int j = 0; j < 8; j++) {
        int nib = (w >> (4 * j)) & 15;
        float val = ((float)nib - z) * s;
        split_store(val, Whi, Wlo, (size_t)(k8 * 8 + j) * N + n);
    }
}

// ---------------- split x into hi/lo bf16 ----------------
__global__ void splitx_kernel(const float* __restrict__ x) {
    int idx = blockIdx.x * blockDim.x + threadIdx.x;
    if (idx >= SEQ * HIDDEN) return;
    split_store(x[idx], g_x_hi, g_x_lo, idx);
}

// ---------------- mma / ldmatrix / cp.async helpers ----------------
__device__ __forceinline__ void ldsm_x4(uint32_t (&r)[4], uint32_t addr) {
    asm volatile("ldmatrix.sync.aligned.m8n8.x4.shared.b16 {%0,%1,%2,%3}, [%4];"
                 : "=r"(r[0]), "=r"(r[1]), "=r"(r[2]), "=r"(r[3]) : "r"(addr));
}
__device__ __forceinline__ void ldsm_x4_t(uint32_t (&r)[4], uint32_t addr) {
    asm volatile("ldmatrix.sync.aligned.m8n8.x4.trans.shared.b16 {%0,%1,%2,%3}, [%4];"
                 : "=r"(r[0]), "=r"(r[1]), "=r"(r[2]), "=r"(r[3]) : "r"(addr));
}
__device__ __forceinline__ void mma_bf16(float (&c)[4], const uint32_t (&a)[4],
                                         uint32_t b0, uint32_t b1) {
    asm volatile("mma.sync.aligned.m16n8k16.row.col.f32.bf16.bf16.f32 "
                 "{%0,%1,%2,%3}, {%4,%5,%6,%7}, {%8,%9}, {%0,%1,%2,%3};"
                 : "+f"(c[0]), "+f"(c[1]), "+f"(c[2]), "+f"(c[3])
                 : "r"(a[0]), "r"(a[1]), "r"(a[2]), "r"(a[3]), "r"(b0), "r"(b1));
}
__device__ __forceinline__ uint32_t pack2bf(float a, float b) {
    uint32_t r;
    asm("cvt.rn.bf16x2.f32 %0, %1, %2;" : "=r"(r) : "f"(b), "f"(a));
    return r;
}
__device__ __forceinline__ void cp_async16(uint32_t saddr, const void* gptr) {
    asm volatile("cp.async.cg.shared.global [%0], [%1], 16;"
                 :: "r"(saddr), "l"(gptr) : "memory");
}
#define CP_COMMIT()  asm volatile("cp.async.commit_group;" ::: "memory")
#define CP_WAIT(n)   asm volatile("cp.async.wait_group %0;" :: "n"(n) : "memory")

// ---------------- split-bf16 tensor-core GEMM, cp.async double-buffered ----------------
// outmode 0: fp32 -> Cext/csel.  outmode 1: split bf16 -> g_v_hi/g_v_lo.
#define GEMM_SMEM_BYTES 65536
__global__ __launch_bounds__(256)
void gemm_bf16split_kernel(int asel, int wsel, float* __restrict__ Cext, int csel,
                           const float* __restrict__ bias, int M, int N, int K,
                           int outmode) {
    extern __shared__ __nv_bfloat16 gsm[];

    const __nv_bfloat16 *Ahi, *Alo;
    asel_get(asel, Ahi, Alo);
    __nv_bfloat16 *Whi_, *Wlo_;
    wsel_get(wsel, Whi_, Wlo_);
    const __nv_bfloat16* Whi = Whi_;
    const __nv_bfloat16* Wlo = Wlo_;

    int tid  = threadIdx.x;
    int lane = tid & 31;
    int wid  = tid >> 5;
    int wm   = wid & 3;
    int wn   = wid >> 2;
    int m0   = blockIdx.y * 128;
    int n0   = blockIdx.x * 128;

    uint32_t uG = (uint32_t)__cvta_generic_to_shared(gsm);

    int idx0 = tid,      idx1 = tid + 256;
    int arow0 = idx0 >> 2, ac0 = idx0 & 3, apc0 = ac0 ^ ((arow0 >> 1) & 3);
    int arow1 = idx1 >> 2, ac1 = idx1 & 3, apc1 = ac1 ^ ((arow1 >> 1) & 3);
    int krow0 = idx0 >> 4, wc0 = idx0 & 15, wpc0 = wc0 ^ (krow0 & 7);
    int krow1 = idx1 >> 4, wc1 = idx1 & 15, wpc1 = wc1 ^ (krow1 & 7);
    uint32_t ad0 = (uint32_t)(arow0 * 32 + apc0 * 8) * 2;
    uint32_t ad1 = (uint32_t)(arow1 * 32 + apc1 * 8) * 2;
    uint32_t wd0 = (uint32_t)(krow0 * 128 + wpc0 * 8) * 2;
    uint32_t wd1 = (uint32_t)(krow1 * 128 + wpc1 * 8) * 2;

    float c[2][8][4];
#pragma unroll
    for (int i = 0; i < 2; i++)
#pragma unroll
        for (int j = 0; j < 8; j++)
#pragma unroll
            for (int l = 0; l < 4; l++) c[i][j][l] = 0.f;

    int T = K / 32;

    auto issue_tile = [&](int kt, int st) {
        int k0 = kt * 32;
        uint32_t sb = uG + (uint32_t)st * 32768u;
        size_t a0 = (size_t)(m0 + arow0) * K + k0 + ac0 * 8;
        size_t a1 = (size_t)(m0 + arow1) * K + k0 + ac1 * 8;
        size_t w0 = (size_t)(k0 + krow0) * N + n0 + wc0 * 8;
        size_t w1 = (size_t)(k0 + krow1) * N + n0 + wc1 * 8;
        cp_async16(sb + ad0,          Ahi + a0);
        cp_async16(sb + ad0 + 8192,   Alo + a0);
        cp_async16(sb + ad1,          Ahi + a1);
        cp_async16(sb + ad1 + 8192,   Alo + a1);
        cp_async16(sb + wd0 + 16384,  Whi + w0);
        cp_async16(sb + wd0 + 24576,  Wlo + w0);
        cp_async16(sb + wd1 + 16384,  Whi + w1);
        cp_async16(sb + wd1 + 24576,  Wlo + w1);
        CP_COMMIT();
    };

    issue_tile(0, 0);
    issue_tile(1, 1);

    for (int t = 0; t < T; t++) {
        if (t == T - 1) CP_WAIT(0); else CP_WAIT(1);
        __syncthreads();

        uint32_t sb   = uG + (uint32_t)(t & 1) * 32768u;
        uint32_t uA   = sb;
        uint32_t uAlo = sb + 8192;
        uint32_t uW   = sb + 16384;
        uint32_t uWlo = sb + 24576;

#pragma unroll
        for (int kk = 0; kk < 2; kk++) {
            uint32_t ahi[2][4], alo[2][4];
#pragma unroll
            for (int mt = 0; mt < 2; mt++) {
                int row = wm * 32 + mt * 16 + (lane & 15);
                int kc  = kk * 2 + (lane >> 4);
                int pc  = kc ^ ((row >> 1) & 3);
                uint32_t off = (uint32_t)(row * 32 + pc * 8) * 2;
                ldsm_x4(ahi[mt], uA + off);
                ldsm_x4(alo[mt], uAlo + off);
            }
#pragma unroll
            for (int np = 0; np < 4; np++) {
                uint32_t bhi[4], blo[4];
                int krow = kk * 16 + (lane & 15);
                int cc   = wn * 8 + np * 2 + (lane >> 4);
                int pcc  = cc ^ (krow & 7);
                uint32_t off = (uint32_t)(krow * 128 + pcc * 8) * 2;
                ldsm_x4_t(bhi, uW + off);
                ldsm_x4_t(blo, uWlo + off);
#pragma unroll
                for (int mt = 0; mt < 2; mt++) {
                    mma_bf16(c[mt][np * 2 + 0], ahi[mt], bhi[0], bhi[1]);
                    mma_bf16(c[mt][np * 2 + 1], ahi[mt], bhi[2], bhi[3]);
                    mma_bf16(c[mt][np * 2 + 0], ahi[mt], blo[0], blo[1]);
                    mma_bf16(c[mt][np * 2 + 1], ahi[mt], blo[2], blo[3]);
                    mma_bf16(c[mt][np * 2 + 0], alo[mt], bhi[0], bhi[1]);
                    mma_bf16(c[mt][np * 2 + 1], alo[mt], bhi[2], bhi[3]);
                }
            }
        }
        __syncthreads();
        if (t + 2 < T) issue_tile(t + 2, t & 1);
    }

    float* C = Cext ? Cext : csel_get(csel);
#pragma unroll
    for (int mt = 0; mt < 2; mt++) {
        int row = m0 + wm * 32 + mt * 16 + (lane >> 2);
#pragma unroll
        for (int nt = 0; nt < 8; nt++) {
            int col = n0 + wn * 64 + nt * 8 + (lane & 3) * 2;
            float b0 = bias ? bias[col] : 0.f;
            float b1 = bias ? bias[col + 1] : 0.f;
            float v00 = c[mt][nt][0] + b0, v01 = c[mt][nt][1] + b1;
            float v10 = c[mt][nt][2] + b0, v11 = c[mt][nt][3] + b1;
            if (outmode == 0) {
                float2 p0 = {v00, v01}, p1 = {v10, v11};
                *(float2*)&C[(size_t)row * N + col]       = p0;
                *(float2*)&C[(size_t)(row + 8) * N + col] = p1;
            } else {
                size_t i0 = (size_t)row * N + col;
                size_t i1 = (size_t)(row + 8) * N + col;
                split_store(v00, g_v_hi, g_v_lo, i0);
                split_store(v01, g_v_hi, g_v_lo, i0 + 1);
                split_store(v10, g_v_hi, g_v_lo, i1);
                split_store(v11, g_v_hi, g_v_lo, i1 + 1);
            }
        }
    }
}

// ---------------- RoPE: fp32 in, split bf16 out (Q pre-scaled by 1/sqrt(HD)) ----------------
template <int NHEADS>
__global__ void rope_split_kernel(const float* __restrict__ cosp,
                                  const float* __restrict__ sinp) {
    int idx = blockIdx.x * blockDim.x + threadIdx.x;
    if (idx >= SEQ * NHEADS * (HD / 2)) return;
    int half = idx & 63;
    int h    = (idx >> 6) % NHEADS;
    int s    = idx / (64 * NHEADS);
    const float* base = (NHEADS == NH ? g_q : g_k) + (size_t)(s * NHEADS + h) * HD;
    float c  = cosp[s * HD + half];
    float sn = sinp[s * HD + half];
    float x1 = base[half];
    float x2 = base[half + 64];
    float r1 = x1 * c - x2 * sn;
    float r2 = x2 * c + x1 * sn;
    const float qs = (NHEADS == NH) ? 0.0883883476483184f : 1.0f;  // 1/sqrt(128) folded into Q
    r1 *= qs; r2 *= qs;
    __nv_bfloat16* hi = (NHEADS == NH) ? g_q_hi : g_k_hi;
    __nv_bfloat16* lo = (NHEADS == NH) ? g_q_lo : g_k_lo;
    size_t o = (size_t)(s * NHEADS + h) * HD;
    split_store(r1, hi, lo, o + half);
    split_store(r2, hi, lo, o + half + 64);
}

// ---------------- tensor-core flash attention (causal, split-bf16, GQA) ----------------
// BM=128 (8 warps x 16 rows), BN=64. Q frags in regs; S frags reused as P frags.
// cp.async double-buffered KV: stage s at byte s*65536; within stage:
//   Khi +0, Klo +16384, Vhi +32768, Vlo +49152.  Q stages into stage-1 region.
#define FLASH_SMEM_BYTES 131072
__global__ __launch_bounds__(256, 1)
void flash_attn_tc_kernel() {
    extern __shared__ __nv_bfloat16 fsm[];
    int tid  = threadIdx.x;
    int lane = tid & 31;
    int wid  = tid >> 5;          // 0..7, 16 rows each
    int qb   = gridDim.x - 1 - blockIdx.x;   // big tiles first
    int h    = blockIdx.y;
    int kvh  = h / REP;
    int r0   = qb * 128;

    uint32_t uS = (uint32_t)__cvta_generic_to_shared(fsm);

    // ---- stage Q into stage-1 region (hi at byte 65536, lo at 98304) ----
    for (int i = tid; i < 128 * 16; i += 256) {
        int row = i >> 4, c = i & 15;
        int pc = c ^ (row & 7);
        size_t src = (size_t)(r0 + row) * QN + h * HD + c * 8;
        *(uint4*)&fsm[32768 + row * 128 + pc * 8] = *(const uint4*)&g_q_hi[src];
        *(uint4*)&fsm[49152 + row * 128 + pc * 8] = *(const uint4*)&g_q_lo[src];
    }
    __syncthreads();

    int nkb = 2 * qb + 2;

    // issue KV tile kb into stage st
    auto issue_kv = [&](int kb, int st) {
        uint32_t sb = uS + (uint32_t)st * 65536u;
        for (int i = tid; i < 64 * 16; i += 256) {
            int row = i >> 4, c = i & 15;
            int pc = c ^ (row & 7);
            size_t src = (size_t)(kb * 64 + row) * KVN + kvh * HD + c * 8;
            uint32_t d = (uint32_t)(row * 256 + pc * 16);
            cp_async16(sb + d,          g_k_hi + src);
            cp_async16(sb + 16384 + d,  g_k_lo + src);
            cp_async16(sb + 32768 + d,  g_v_hi + src);
            cp_async16(sb + 49152 + d,  g_v_lo + src);
        }
        CP_COMMIT();
    };

    // kb=0 -> stage 0 (disjoint from Q's stage-1 region) — start it flowing now
    issue_kv(0, 0);

    // extract Q fragments from stage-1 region
    uint32_t qhi[8][4], qlo[8][4];
    {
        int mrow = wid * 16 + (lane & 15);
#pragma unroll
        for (int kc = 0; kc < 8; kc++) {
            int ch = kc * 2 + (lane >> 4);
            int pc = ch ^ (mrow & 7);
            uint32_t off = (uint32_t)(mrow * 128 + pc * 8) * 2;
            ldsm_x4(qhi[kc], uS + 65536 + off);
            ldsm_x4(qlo[kc], uS + 98304 + off);
        }
    }
    __syncthreads();   // Q consumed; stage-1 region free

    issue_kv(1, 1);

    float o_acc[16][4];
#pragma unroll
    for (int i = 0; i < 16; i++)
#pragma unroll
        for (int j = 0; j < 4; j++) o_acc[i][j] = 0.f;
    float m_r[2] = {-1e30f, -1e30f};
    float l_r[2] = {0.f, 0.f};

    int krow_base = (lane & 7) + ((lane >> 4) << 3);
    int kch_sel   = (lane >> 3) & 1;
    int vrow_base = (lane & 7) + (((lane >> 3) & 1) << 3);
    int vch_base  = lane >> 4;

    for (int kb = 0; kb < nkb; kb++) {
        if (kb == nkb - 1) CP_WAIT(0); else CP_WAIT(1);
        __syncthreads();

        uint32_t sb = uS + (uint32_t)(kb & 1) * 65536u;

        // ---- S = Q K^T (scale pre-folded into Q) ----
        float s[8][4];
#pragma unroll
        for (int i = 0; i < 8; i++)
#pragma unroll
            for (int j = 0; j < 4; j++) s[i][j] = 0.f;

#pragma unroll
        for (int np = 0; np < 4; np++) {
            int nrow = np * 16 + krow_base;
            uint32_t rowoff = (uint32_t)nrow * 256;
            int rx = nrow & 7;
#pragma unroll
            for (int kc = 0; kc < 8; kc++) {
                int pc = (kc * 2 + kch_sel) ^ rx;
                uint32_t off = rowoff + (uint32_t)pc * 16;
                uint32_t bh[4], bl[4];
                ldsm_x4(bh, sb + off);
                ldsm_x4(bl, sb + 16384 + off);
                mma_bf16(s[np * 2 + 0], qhi[kc], bh[0], bh[1]);
                mma_bf16(s[np * 2 + 1], qhi[kc], bh[2], bh[3]);
                mma_bf16(s[np * 2 + 0], qhi[kc], bl[0], bl[1]);
                mma_bf16(s[np * 2 + 1], qhi[kc], bl[2], bl[3]);
                mma_bf16(s[np * 2 + 0], qlo[kc], bh[0], bh[1]);
                mma_bf16(s[np * 2 + 1], qlo[kc], bh[2], bh[3]);
            }
        }

        // ---- causal mask ----
        if (kb >= 2 * qb) {
#pragma unroll
            for (int nt = 0; nt < 8; nt++)
#pragma unroll
                for (int e = 0; e < 4; e++) {
                    int col = kb * 64 + nt * 8 + 2 * (lane & 3) + (e & 1);
                    int row = r0 + wid * 16 + (lane >> 2) + (e >> 1) * 8;
                    if (col > row) s[nt][e] = -1e30f;
                }
        }

        // ---- online softmax ----
#pragma unroll
        for (int r = 0; r < 2; r++) {
            float mx = -1e30f;
#pragma unroll
            for (int nt = 0; nt < 8; nt++)
                mx = fmaxf(mx, fmaxf(s[nt][2 * r], s[nt][2 * r + 1]));
            mx = fmaxf(mx, __shfl_xor_sync(0xffffffffu, mx, 1));
            mx = fmaxf(mx, __shfl_xor_sync(0xffffffffu, mx, 2));
            float mnew = fmaxf(m_r[r], mx);
            float alpha = __expf(m_r[r] - mnew);
            m_r[r] = mnew;
            float ps = 0.f;
#pragma unroll
            for (int nt = 0; nt < 8; nt++) {
                s[nt][2 * r]     = __expf(s[nt][2 * r] - mnew);
                s[nt][2 * r + 1] = __expf(s[nt][2 * r + 1] - mnew);
                ps += s[nt][2 * r] + s[nt][2 * r + 1];
            }
            l_r[r] = l_r[r] * alpha + ps;
#pragma unroll
            for (int nt = 0; nt < 16; nt++) {
                o_acc[nt][2 * r]     *= alpha;
                o_acc[nt][2 * r + 1] *= alpha;
            }
        }

        // ---- O += P V ----
#pragma unroll
        for (int kc = 0; kc < 4; kc++) {
            float p00 = s[2 * kc][0],     p01 = s[2 * kc][1];
            float p10 = s[2 * kc][2],     p11 = s[2 * kc][3];
            float p20 = s[2 * kc + 1][0], p21 = s[2 * kc + 1][1];
            float p30 = s[2 * kc + 1][2], p31 = s[2 * kc + 1][3];
            uint32_t phi[4], plo[4];
            phi[0] = pack2bf(p00, p01);
            phi[1] = pack2bf(p10, p11);
            phi[2] = pack2bf(p20, p21);
            phi[3] = pack2bf(p30, p31);
            plo[0] = pack2bf(p00 - __bfloat162float(__float2bfloat16(p00)),
                             p01 - __bfloat162float(__float2bfloat16(p01)));
            plo[1] = pack2bf(p10 - __bfloat162float(__float2bfloat16(p10)),
                             p11 - __bfloat162float(__float2bfloat16(p11)));
            plo[2] = pack2bf(p20 - __bfloat162float(__float2bfloat16(p20)),
                             p21 - __bfloat162float(__float2bfloat16(p21)));
            plo[3] = pack2bf(p30 - __bfloat162float(__float2bfloat16(p30)),
                             p31 - __bfloat162float(__float2bfloat16(p31)));

            int krow = kc * 16 + vrow_base;
            uint32_t rowoff = (uint32_t)krow * 256;
            int rx = krow & 7;
#pragma unroll
            for (int np = 0; np < 8; np++) {
                int pc = (np * 2 + vch_base) ^ rx;
                uint32_t off = rowoff + (uint32_t)pc * 16;
                uint32_t vh[4], vl[4];
                ldsm_x4_t(vh, sb + 32768 + off);
                ldsm_x4_t(vl, sb + 49152 + off);
                mma_bf16(o_acc[np * 2 + 0], phi, vh[0], vh[1]);
                mma_bf16(o_acc[np * 2 + 1], phi, vh[2], vh[3]);
                mma_bf16(o_acc[np * 2 + 0], phi, vl[0], vl[1]);
                mma_bf16(o_acc[np * 2 + 1], phi, vl[2], vl[3]);
                mma_bf16(o_acc[np * 2 + 0], plo, vh[0], vh[1]);
                mma_bf16(o_acc[np * 2 + 1], plo, vh[2], vh[3]);
            }
        }
        __syncthreads();   // stage (kb&1) fully consumed by all warps
        if (kb + 2 < nkb) issue_kv(kb + 2, kb & 1);
    }

    // ---- epilogue: normalize, split-store to g_a ----
    float l0 = l_r[0];
    l0 += __shfl_xor_sync(0xffffffffu, l0, 1);
    l0 += __shfl_xor_sync(0xffffffffu, l0, 2);
    float l1 = l_r[1];
    l1 += __shfl_xor_sync(0xffffffffu, l1, 1);
    l1 += __shfl_xor_sync(0xffffffffu, l1, 2);
    float inv0 = 1.f / l0, inv1 = 1.f / l1;

    int row = r0 + wid * 16 + (lane >> 2);
#pragma unroll
    for (int nt = 0; nt < 16; nt++) {
        int col = h * HD + nt * 8 + 2 * (lane & 3);
        size_t i0 = (size_t)row * QN + col;
        size_t i1 = i0 + (size_t)8 * QN;
        float v0 = o_acc[nt][0] * inv0, v1 = o_acc[nt][1] * inv0;
        float w0 = o_acc[nt][2] * inv1, w1 = o_acc[nt][3] * inv1;
        __nv_bfloat16 h0 = __float2bfloat16(v0), h1 = __float2bfloat16(v1);
        __nv_bfloat16 g0 = __float2bfloat16(w0), g1 = __float2bfloat16(w1);
        __nv_bfloat162 ph; ph.x = h0; ph.y = h1;
        __nv_bfloat162 pg; pg.x = g0; pg.y = g1;
        *(__nv_bfloat162*)&g_a_hi[i0] = ph;
        *(__nv_bfloat162*)&g_a_hi[i1] = pg;
        __nv_bfloat162 pl, pm;
        pl.x = __float2bfloat16(v0 - __bfloat162float(h0));
        pl.y = __float2bfloat16(v1 - __bfloat162float(h1));
        pm.x = __float2bfloat16(w0 - __bfloat162float(g0));
        pm.y = __float2bfloat16(w1 - __bfloat162float(g1));
        *(__nv_bfloat162*)&g_a_lo[i0] = pl;
        *(__nv_bfloat162*)&g_a_lo[i1] = pm;
    }
}

// ---------------- host launch ----------------
extern "C" void kernel_launch(void* const* d_in, const int* in_sizes, int n_in,
                              void* d_out, int out_size) {
    const float* x    = (const float*)d_in[0];
    const float* cosp = (const float*)d_in[1];
    const float* sinp = (const float*)d_in[2];
    const float* q_sc = (const float*)d_in[3];
    const float* q_b  = (const float*)d_in[4];
    const float* k_sc = (const float*)d_in[5];
    const float* k_b  = (const float*)d_in[6];
    const float* v_sc = (const float*)d_in[7];
    const float* v_b  = (const float*)d_in[8];
    const float* o_sc = (const float*)d_in[9];
    const int*   q_qw = (const int*)d_in[10];
    const int*   q_qz = (const int*)d_in[11];
    const int*   k_qw = (const int*)d_in[12];
    const int*   k_qz = (const int*)d_in[13];
    const int*   v_qw = (const int*)d_in[14];
    const int*   v_qz = (const int*)d_in[15];
    const int*   o_qw = (const int*)d_in[16];
    const int*   o_qz = (const int*)d_in[17];
    float* out = (float*)d_out;

    cudaFuncSetAttribute(flash_attn_tc_kernel,
                         cudaFuncAttributeMaxDynamicSharedMemorySize,
                         FLASH_SMEM_BYTES);
    cudaFuncSetAttribute(gemm_bf16split_kernel,
                         cudaFuncAttributeMaxDynamicSharedMemorySize,
                         GEMM_SMEM_BYTES);

    // dequant weights -> split bf16
    {
        int n, thr = 256;
        n = (HIDDEN / 8) * QN;
        dequant_kernel<<<(n + thr - 1) / thr, thr>>>(q_qw, q_sc, q_qz, 0, HIDDEN / 8, QN);
        n = (HIDDEN / 8) * KVN;
        dequant_kernel<<<(n + thr - 1) / thr, thr>>>(k_qw, k_sc, k_qz, 1, HIDDEN / 8, KVN);
        dequant_kernel<<<(n + thr - 1) / thr, thr>>>(v_qw, v_sc, v_qz, 2, HIDDEN / 8, KVN);
        n = (QN / 8) * HIDDEN;
        dequant_kernel<<<(n + thr - 1) / thr, thr>>>(o_qw, o_sc, o_qz, 3, QN / 8, HIDDEN);
    }

    // split x
    splitx_kernel<<<(SEQ * HIDDEN + 255) / 256, 256>>>(x);

    // projections: Q,K -> fp32 (rope follows); V -> split bf16 directly
    {
        dim3 b(256);
        gemm_bf16split_kernel<<<dim3(QN / 128, SEQ / 128), b, GEMM_SMEM_BYTES>>>(0, 0, nullptr, 1, q_b, SEQ, QN, HIDDEN, 0);
        gemm_bf16split_kernel<<<dim3(KVN / 128, SEQ / 128), b, GEMM_SMEM_BYTES>>>(0, 1, nullptr, 2, k_b, SEQ, KVN, HIDDEN, 0);
        gemm_bf16split_kernel<<<dim3(KVN / 128, SEQ / 128), b, GEMM_SMEM_BYTES>>>(0, 2, nullptr, 0, v_b, SEQ, KVN, HIDDEN, 1);
    }

    // RoPE -> split bf16 (Q pre-scaled)
    {
        int nq = SEQ * NH * (HD / 2);
        rope_split_kernel<NH><<<(nq + 255) / 256, 256>>>(cosp, sinp);
        int nk = SEQ * NKV * (HD / 2);
        rope_split_kernel<NKV><<<(nk + 255) / 256, 256>>>(cosp, sinp);
    }

    // tensor-core flash attention
    {
        dim3 grid(SEQ / 128, NH);
        flash_attn_tc_kernel<<<grid, 256, FLASH_SMEM_BYTES>>>();
    }

    // O projection -> d_out
    gemm_bf16split_kernel<<<dim3(HIDDEN / 128, SEQ / 128), 256, GEMM_SMEM_BYTES>>>(1, 3, out, 0, nullptr, SEQ, HIDDEN, QN, 0);
}